// round 1
// baseline (speedup 1.0000x reference)
#include <cuda_runtime.h>
#include <cuda_bf16.h>

#define N_NODES 100000
#define N_EDGES 640000
#define D 128
#define NB_SCAN ((N_NODES + 1023) / 1024)   // 98

// ---------------- scratch (device globals: no allocation allowed) ----------
__device__ __align__(16) float g_mean[N_NODES * D];
__device__ __align__(16) float g_hA[N_NODES * D];
__device__ __align__(16) float g_hB[N_NODES * D];
__device__ __align__(16) float g_pa[N_NODES * D];
__device__ __align__(16) float g_pb[N_NODES * D];
__device__ int g_cnt[N_NODES];
__device__ int g_rowptr[N_NODES + 1];
__device__ int g_csr[N_EDGES];
__device__ int g_bsum[NB_SCAN];
__device__ int g_boff[NB_SCAN];

// ---------------- CSR construction ----------------------------------------
__global__ void k_zero_cnt() {
    int i = blockIdx.x * blockDim.x + threadIdx.x;
    if (i < N_NODES) g_cnt[i] = 0;
}

__global__ void k_hist(const int* __restrict__ dst) {
    int e = blockIdx.x * blockDim.x + threadIdx.x;
    if (e < N_EDGES) atomicAdd(&g_cnt[dst[e]], 1);
}

__global__ void k_blockreduce() {
    __shared__ int sh[1024];
    int i = blockIdx.x * 1024 + threadIdx.x;
    sh[threadIdx.x] = (i < N_NODES) ? g_cnt[i] : 0;
    __syncthreads();
    for (int o = 512; o > 0; o >>= 1) {
        if (threadIdx.x < o) sh[threadIdx.x] += sh[threadIdx.x + o];
        __syncthreads();
    }
    if (threadIdx.x == 0) g_bsum[blockIdx.x] = sh[0];
}

__global__ void k_scan_bsum() {
    if (threadIdx.x == 0 && blockIdx.x == 0) {
        int run = 0;
        for (int b = 0; b < NB_SCAN; b++) { g_boff[b] = run; run += g_bsum[b]; }
        g_rowptr[N_NODES] = run;   // == N_EDGES
    }
}

__global__ void k_blockscan() {
    __shared__ int sh[1024];
    int tid = threadIdx.x;
    int i = blockIdx.x * 1024 + tid;
    int v = (i < N_NODES) ? g_cnt[i] : 0;
    sh[tid] = v;
    __syncthreads();
    for (int o = 1; o < 1024; o <<= 1) {
        int t = (tid >= o) ? sh[tid - o] : 0;
        __syncthreads();
        sh[tid] += t;
        __syncthreads();
    }
    if (i < N_NODES) g_rowptr[i] = g_boff[blockIdx.x] + sh[tid] - v;  // exclusive
}

__global__ void k_place(const int* __restrict__ src, const int* __restrict__ dst) {
    int e = blockIdx.x * blockDim.x + threadIdx.x;
    if (e < N_EDGES) {
        int d = dst[e];
        int slot = g_rowptr[d] + atomicAdd(&g_cnt[d], 1);
        g_csr[slot] = src[e];
    }
}

// ---------------- mean aggregation (gather, warp-per-node) -----------------
__global__ void k_agg(const float* __restrict__ xin) {
    int gw   = (blockIdx.x * blockDim.x + threadIdx.x) >> 5;
    int lane = threadIdx.x & 31;
    if (gw >= N_NODES) return;
    int beg = g_rowptr[gw], end = g_rowptr[gw + 1];
    float4 acc = make_float4(0.f, 0.f, 0.f, 0.f);
    for (int e = beg; e < end; e++) {
        int s = g_csr[e];
        float4 v = *(const float4*)&xin[s * D + lane * 4];
        acc.x += v.x; acc.y += v.y; acc.z += v.z; acc.w += v.w;
    }
    int deg = end - beg;
    float inv = 1.0f / (float)(deg > 1 ? deg : 1);
    acc.x *= inv; acc.y *= inv; acc.z *= inv; acc.w *= inv;
    *(float4*)&g_mean[gw * D + lane * 4] = acc;
}

// ---------------- fp32 GEMM: out[M,128] = A1@W1 (+ A2@W2) (+ bias) --------
// W stored row-major [K=128][N=128] (i.e. [in,out]).
// Tile: 128 rows x 128 cols per block, 256 threads, 8x8 per thread, K-tiles of 16.
__global__ __launch_bounds__(256) void k_gemm(
    const float* __restrict__ A1, const float* __restrict__ W1,
    const float* __restrict__ A2, const float* __restrict__ W2,
    const float* __restrict__ bias, float* __restrict__ out, int M)
{
    __shared__ float  As[128][17];
    __shared__ float4 Bs4[16][32];           // [16][128] floats
    float* Bs = (float*)Bs4;

    int tid = threadIdx.x;
    int tx = tid & 15, ty = tid >> 4;
    int m0 = blockIdx.x * 128;

    float acc[8][8];
    #pragma unroll
    for (int i = 0; i < 8; i++)
        #pragma unroll
        for (int j = 0; j < 8; j++) acc[i][j] = 0.f;

    int ntiles = (A2 != nullptr) ? 16 : 8;
    for (int kt = 0; kt < ntiles; kt++) {
        const float* Asrc = (kt < 8) ? A1 : A2;
        const float* Wsrc = (kt < 8) ? W1 : W2;
        int kb = (kt & 7) * 16;

        // A tile: 128 rows x 16 k  (512 float4)
        for (int l = tid; l < 512; l += 256) {
            int r = l >> 2, c = l & 3;
            int row = m0 + r;
            float4 v = make_float4(0.f, 0.f, 0.f, 0.f);
            if (row < M) v = *(const float4*)&Asrc[row * D + kb + 4 * c];
            As[r][4 * c + 0] = v.x; As[r][4 * c + 1] = v.y;
            As[r][4 * c + 2] = v.z; As[r][4 * c + 3] = v.w;
        }
        // W tile: 16 k x 128 cols (512 float4, contiguous rows)
        for (int l = tid; l < 512; l += 256) {
            int r = l >> 5, c = l & 31;
            Bs4[r][c] = *(const float4*)&Wsrc[(kb + r) * D + 4 * c];
        }
        __syncthreads();

        #pragma unroll
        for (int kk = 0; kk < 16; kk++) {
            float a[8], b[8];
            #pragma unroll
            for (int i = 0; i < 8; i++) a[i] = As[ty * 8 + i][kk];
            #pragma unroll
            for (int j = 0; j < 8; j++) b[j] = Bs[kk * 128 + tx + 16 * j];
            #pragma unroll
            for (int i = 0; i < 8; i++)
                #pragma unroll
                for (int j = 0; j < 8; j++) acc[i][j] += a[i] * b[j];
        }
        __syncthreads();
    }

    float bb[8];
    #pragma unroll
    for (int j = 0; j < 8; j++) bb[j] = (bias != nullptr) ? bias[tx + 16 * j] : 0.f;
    #pragma unroll
    for (int i = 0; i < 8; i++) {
        int row = m0 + ty * 8 + i;
        if (row < M) {
            #pragma unroll
            for (int j = 0; j < 8; j++)
                out[row * D + tx + 16 * j] = acc[i][j] + bb[j];
        }
    }
}

// ---------------- edge scoring: relu(PA[s] + PB[d]) . Wp2 + bp2 ------------
// PA already contains bp1 (folded in as GEMM bias).
__global__ void k_edge(const int* __restrict__ s1, const int* __restrict__ d1,
                       const int* __restrict__ s2, const int* __restrict__ d2,
                       const float* __restrict__ Wp2, const float* __restrict__ bp2,
                       float* __restrict__ out)
{
    int gw   = (blockIdx.x * blockDim.x + threadIdx.x) >> 5;
    int lane = threadIdx.x & 31;
    if (gw >= 2 * N_EDGES) return;
    int ss, dd;
    if (gw < N_EDGES) { ss = s1[gw]; dd = d1[gw]; }
    else              { ss = s2[gw - N_EDGES]; dd = d2[gw - N_EDGES]; }

    float4 a = *(const float4*)&g_pa[ss * D + lane * 4];
    float4 b = *(const float4*)&g_pb[dd * D + lane * 4];
    float4 w = *(const float4*)&Wp2[lane * 4];

    float p = fmaxf(a.x + b.x, 0.f) * w.x
            + fmaxf(a.y + b.y, 0.f) * w.y
            + fmaxf(a.z + b.z, 0.f) * w.z
            + fmaxf(a.w + b.w, 0.f) * w.w;
    #pragma unroll
    for (int o = 16; o > 0; o >>= 1) p += __shfl_xor_sync(0xffffffffu, p, o);
    if (lane == 0) out[gw] = p + bp2[0];
}

// ---------------- launch ----------------------------------------------------
extern "C" void kernel_launch(void* const* d_in, const int* in_sizes, int n_in,
                              void* d_out, int out_size)
{
    const float* x    = (const float*)d_in[0];
    const int*   src  = (const int*)d_in[1];
    const int*   dst  = (const int*)d_in[2];
    const int*   nsrc = (const int*)d_in[3];
    const int*   ndst = (const int*)d_in[4];
    const float* Ws1 = (const float*)d_in[5],  *Wn1 = (const float*)d_in[6],  *b1 = (const float*)d_in[7];
    const float* Ws2 = (const float*)d_in[8],  *Wn2 = (const float*)d_in[9],  *b2 = (const float*)d_in[10];
    const float* Ws3 = (const float*)d_in[11], *Wn3 = (const float*)d_in[12], *b3 = (const float*)d_in[13];
    const float* Wp1 = (const float*)d_in[14], *bp1 = (const float*)d_in[15];
    const float* Wp2 = (const float*)d_in[16], *bp2 = (const float*)d_in[17];
    float* out = (float*)d_out;

    float *p_mean, *p_hA, *p_hB, *p_pa, *p_pb;
    cudaGetSymbolAddress((void**)&p_mean, g_mean);
    cudaGetSymbolAddress((void**)&p_hA, g_hA);
    cudaGetSymbolAddress((void**)&p_hB, g_hB);
    cudaGetSymbolAddress((void**)&p_pa, g_pa);
    cudaGetSymbolAddress((void**)&p_pb, g_pb);

    // --- build CSR (per-launch; deterministic inputs) ---
    k_zero_cnt<<<(N_NODES + 255) / 256, 256>>>();
    k_hist<<<(N_EDGES + 255) / 256, 256>>>(dst);
    k_blockreduce<<<NB_SCAN, 1024>>>();
    k_scan_bsum<<<1, 32>>>();
    k_blockscan<<<NB_SCAN, 1024>>>();
    k_zero_cnt<<<(N_NODES + 255) / 256, 256>>>();
    k_place<<<(N_EDGES + 255) / 256, 256>>>(src, dst);

    const int aggBlocks  = (N_NODES * 32 + 255) / 256;
    const int gemmBlocks = (N_NODES + 127) / 128;

    // --- layer 1: h = x@Ws1 + mean(x)@Wn1 + b1 ---
    k_agg<<<aggBlocks, 256>>>(x);
    k_gemm<<<gemmBlocks, 256>>>(x, Ws1, p_mean, Wn1, b1, p_hA, N_NODES);
    // --- layer 2 ---
    k_agg<<<aggBlocks, 256>>>(p_hA);
    k_gemm<<<gemmBlocks, 256>>>(p_hA, Ws2, p_mean, Wn2, b2, p_hB, N_NODES);
    // --- layer 3 ---
    k_agg<<<aggBlocks, 256>>>(p_hB);
    k_gemm<<<gemmBlocks, 256>>>(p_hB, Ws3, p_mean, Wn3, b3, p_hA, N_NODES);

    // --- predictor projections: PA = h@Wp1_top + bp1, PB = h@Wp1_bot ---
    k_gemm<<<gemmBlocks, 256>>>(p_hA, Wp1, nullptr, nullptr, bp1, p_pa, N_NODES);
    k_gemm<<<gemmBlocks, 256>>>(p_hA, Wp1 + 128 * D, nullptr, nullptr, nullptr, p_pb, N_NODES);

    // --- edge scores: [pos(E), neg(E)] ---
    k_edge<<<(2 * N_EDGES * 32 + 255) / 256, 256>>>(src, dst, nsrc, ndst, Wp2, bp2, out);
}

// round 2
// speedup vs baseline: 1.3179x; 1.3179x over previous
#include <cuda_runtime.h>
#include <cuda_bf16.h>
#include <cstdint>

#define N_NODES 100000
#define N_EDGES 640000
#define D 128
#define NB_SCAN ((N_NODES + 1023) / 1024)   // 98

typedef __nv_bfloat16 bf16;
typedef __nv_bfloat162 bf162;

// ---------------- scratch (device globals: no allocation allowed) ----------
__device__ __align__(16) float g_hA[N_NODES * D];
__device__ __align__(16) float g_hB[N_NODES * D];
__device__ __align__(16) float g_pa[N_NODES * D];
__device__ __align__(16) float g_pb[N_NODES * D];
// bf16 hi/lo pairs
__device__ __align__(16) bf16 g_xbh[N_NODES * D];
__device__ __align__(16) bf16 g_xbl[N_NODES * D];
__device__ __align__(16) bf16 g_mbh[N_NODES * D];
__device__ __align__(16) bf16 g_mbl[N_NODES * D];
__device__ __align__(16) bf16 g_h1h[N_NODES * D];
__device__ __align__(16) bf16 g_h1l[N_NODES * D];
__device__ __align__(16) bf16 g_h2h[N_NODES * D];
__device__ __align__(16) bf16 g_h2l[N_NODES * D];
// packed weights: rows [Ws1|Wn1|Ws2|Wn2|Ws3|Wn3|Wp1(256 rows)] = 1024 x 128
__device__ __align__(16) bf16 g_wh[1024 * D];
__device__ __align__(16) bf16 g_wl[1024 * D];
// CSR
__device__ int g_cnt[N_NODES];
__device__ int g_rowptr[N_NODES + 1];
__device__ int g_csr[N_EDGES];
__device__ int g_bsum[NB_SCAN];
__device__ int g_boff[NB_SCAN];

// ---------------- CSR construction ----------------------------------------
__global__ void k_zero_cnt() {
    int i = blockIdx.x * blockDim.x + threadIdx.x;
    if (i < N_NODES) g_cnt[i] = 0;
}
__global__ void k_hist(const int* __restrict__ dst) {
    int e = blockIdx.x * blockDim.x + threadIdx.x;
    if (e < N_EDGES) atomicAdd(&g_cnt[dst[e]], 1);
}
__global__ void k_blockreduce() {
    __shared__ int sh[1024];
    int i = blockIdx.x * 1024 + threadIdx.x;
    sh[threadIdx.x] = (i < N_NODES) ? g_cnt[i] : 0;
    __syncthreads();
    for (int o = 512; o > 0; o >>= 1) {
        if (threadIdx.x < o) sh[threadIdx.x] += sh[threadIdx.x + o];
        __syncthreads();
    }
    if (threadIdx.x == 0) g_bsum[blockIdx.x] = sh[0];
}
__global__ void k_scan_bsum() {
    if (threadIdx.x == 0 && blockIdx.x == 0) {
        int run = 0;
        for (int b = 0; b < NB_SCAN; b++) { g_boff[b] = run; run += g_bsum[b]; }
        g_rowptr[N_NODES] = run;
    }
}
__global__ void k_blockscan() {
    __shared__ int sh[1024];
    int tid = threadIdx.x;
    int i = blockIdx.x * 1024 + tid;
    int v = (i < N_NODES) ? g_cnt[i] : 0;
    sh[tid] = v;
    __syncthreads();
    for (int o = 1; o < 1024; o <<= 1) {
        int t = (tid >= o) ? sh[tid - o] : 0;
        __syncthreads();
        sh[tid] += t;
        __syncthreads();
    }
    if (i < N_NODES) g_rowptr[i] = g_boff[blockIdx.x] + sh[tid] - v;
}
__global__ void k_place(const int* __restrict__ src, const int* __restrict__ dst) {
    int e = blockIdx.x * blockDim.x + threadIdx.x;
    if (e < N_EDGES) {
        int d = dst[e];
        int slot = g_rowptr[d] + atomicAdd(&g_cnt[d], 1);
        g_csr[slot] = src[e];
    }
}

// ---------------- conversions ----------------------------------------------
__device__ __forceinline__ void split_bf16(float v, bf16& h, bf16& l) {
    h = __float2bfloat16_rn(v);
    l = __float2bfloat16_rn(v - __bfloat162float(h));
}

__global__ void k_cvt4(const float* __restrict__ in, bf16* __restrict__ oh,
                       bf16* __restrict__ ol, int n4) {
    int i = blockIdx.x * blockDim.x + threadIdx.x;
    if (i >= n4) return;
    float4 v = ((const float4*)in)[i];
    bf16 hx, hy, hz, hw, lx, ly, lz, lw;
    split_bf16(v.x, hx, lx); split_bf16(v.y, hy, ly);
    split_bf16(v.z, hz, lz); split_bf16(v.w, hw, lw);
    bf162* ph = (bf162*)&oh[i * 4];
    bf162* pl = (bf162*)&ol[i * 4];
    ph[0] = __halves2bfloat162(hx, hy); ph[1] = __halves2bfloat162(hz, hw);
    pl[0] = __halves2bfloat162(lx, ly); pl[1] = __halves2bfloat162(lz, lw);
}

__global__ void k_cvt_w(const float* Ws1, const float* Wn1,
                        const float* Ws2, const float* Wn2,
                        const float* Ws3, const float* Wn3,
                        const float* Wp1) {
    int i = blockIdx.x * blockDim.x + threadIdx.x;   // 0 .. 1024*128-1
    if (i >= 1024 * D) return;
    int row = i >> 7, col = i & 127;
    const float* s; int lr;
    if      (row < 128)  { s = Ws1; lr = row; }
    else if (row < 256)  { s = Wn1; lr = row - 128; }
    else if (row < 384)  { s = Ws2; lr = row - 256; }
    else if (row < 512)  { s = Wn2; lr = row - 384; }
    else if (row < 640)  { s = Ws3; lr = row - 512; }
    else if (row < 768)  { s = Wn3; lr = row - 640; }
    else                 { s = Wp1; lr = row - 768; }
    float v = s[lr * D + col];
    bf16 h, l; split_bf16(v, h, l);
    g_wh[i] = h; g_wl[i] = l;
}

// ---------------- mean aggregation (gather, warp-per-node) -> bf16 pair ----
__global__ void k_agg(const float* __restrict__ xin) {
    int gw   = (blockIdx.x * blockDim.x + threadIdx.x) >> 5;
    int lane = threadIdx.x & 31;
    if (gw >= N_NODES) return;
    int beg = g_rowptr[gw], end = g_rowptr[gw + 1];
    float4 acc = make_float4(0.f, 0.f, 0.f, 0.f);
    for (int e = beg; e < end; e++) {
        int s = g_csr[e];
        float4 v = *(const float4*)&xin[s * D + lane * 4];
        acc.x += v.x; acc.y += v.y; acc.z += v.z; acc.w += v.w;
    }
    int deg = end - beg;
    float inv = 1.0f / (float)(deg > 1 ? deg : 1);
    acc.x *= inv; acc.y *= inv; acc.z *= inv; acc.w *= inv;
    bf16 hx, hy, hz, hw, lx, ly, lz, lw;
    split_bf16(acc.x, hx, lx); split_bf16(acc.y, hy, ly);
    split_bf16(acc.z, hz, lz); split_bf16(acc.w, hw, lw);
    int idx = gw * D + lane * 4;
    bf162* ph = (bf162*)&g_mbh[idx];
    bf162* pl = (bf162*)&g_mbl[idx];
    ph[0] = __halves2bfloat162(hx, hy); ph[1] = __halves2bfloat162(hz, hw);
    pl[0] = __halves2bfloat162(lx, ly); pl[1] = __halves2bfloat162(lz, lw);
}

// ---------------- tensor-core GEMM (3-term bf16 split) ---------------------
// out[M,128] = (A1|A2)[M,K] @ W[K,128] + bias ; A,W given as bf16 hi/lo pairs.
// Block: 128x128 tile, 256 thr (8 warps, warp tile 64x32), K-chunks of 32.
__device__ __forceinline__ void ldsm4(uint32_t& r0, uint32_t& r1, uint32_t& r2,
                                      uint32_t& r3, uint32_t addr) {
    asm volatile("ldmatrix.sync.aligned.m8n8.x4.shared.b16 {%0,%1,%2,%3}, [%4];"
                 : "=r"(r0), "=r"(r1), "=r"(r2), "=r"(r3) : "r"(addr));
}
__device__ __forceinline__ void ldsm4t(uint32_t& r0, uint32_t& r1, uint32_t& r2,
                                       uint32_t& r3, uint32_t addr) {
    asm volatile("ldmatrix.sync.aligned.m8n8.x4.trans.shared.b16 {%0,%1,%2,%3}, [%4];"
                 : "=r"(r0), "=r"(r1), "=r"(r2), "=r"(r3) : "r"(addr));
}
__device__ __forceinline__ void mma_bf16(float* c, const uint32_t* a, const uint32_t* b) {
    asm volatile(
        "mma.sync.aligned.m16n8k16.row.col.f32.bf16.bf16.f32 "
        "{%0,%1,%2,%3},{%4,%5,%6,%7},{%8,%9},{%0,%1,%2,%3};"
        : "+f"(c[0]), "+f"(c[1]), "+f"(c[2]), "+f"(c[3])
        : "r"(a[0]), "r"(a[1]), "r"(a[2]), "r"(a[3]), "r"(b[0]), "r"(b[1]));
}

#define APITCH 40
#define BPITCH 136

__global__ __launch_bounds__(256) void k_gemm_tc(
    const bf16* __restrict__ A1h, const bf16* __restrict__ A1l,
    const bf16* __restrict__ A2h, const bf16* __restrict__ A2l,
    const bf16* __restrict__ Wh,  const bf16* __restrict__ Wl,
    const float* __restrict__ bias,
    float* __restrict__ outf,
    bf16* __restrict__ outh, bf16* __restrict__ outl,
    int M, int K)
{
    __shared__ bf16 Ash[128 * APITCH];
    __shared__ bf16 Asl[128 * APITCH];
    __shared__ bf16 Bsh[32 * BPITCH];
    __shared__ bf16 Bsl[32 * BPITCH];

    int tid = threadIdx.x;
    int wid = tid >> 5, lane = tid & 31;
    int warp_m = (wid >> 2) * 64;
    int warp_n = (wid & 3) * 32;
    int m0 = blockIdx.x * 128;

    float c[4][4][4];
    #pragma unroll
    for (int i = 0; i < 4; i++)
        #pragma unroll
        for (int j = 0; j < 4; j++)
            #pragma unroll
            for (int q = 0; q < 4; q++) c[i][j][q] = 0.f;

    const int4 zero4 = make_int4(0, 0, 0, 0);

    for (int kb = 0; kb < K; kb += 32) {
        const bf16* Ah = (kb < 128) ? A1h : A2h;
        const bf16* Al = (kb < 128) ? A1l : A2l;
        int ac = kb & 127;
        // A tile 128x32 : 512 int4 per operand
        for (int l = tid; l < 512; l += 256) {
            int r = l >> 2, c8 = l & 3;
            int row = m0 + r;
            int4 vh = zero4, vl = zero4;
            if (row < M) {
                vh = *(const int4*)&Ah[row * D + ac + 8 * c8];
                vl = *(const int4*)&Al[row * D + ac + 8 * c8];
            }
            *(int4*)&Ash[r * APITCH + 8 * c8] = vh;
            *(int4*)&Asl[r * APITCH + 8 * c8] = vl;
        }
        // B tile 32x128 : 512 int4 per operand
        for (int l = tid; l < 512; l += 256) {
            int r = l >> 4, c8 = l & 15;
            *(int4*)&Bsh[r * BPITCH + 8 * c8] = *(const int4*)&Wh[(kb + r) * D + 8 * c8];
            *(int4*)&Bsl[r * BPITCH + 8 * c8] = *(const int4*)&Wl[(kb + r) * D + 8 * c8];
        }
        __syncthreads();

        #pragma unroll
        for (int t = 0; t < 3; t++) {
            const bf16* Asm = (t == 2) ? Asl : Ash;
            const bf16* Bsm = (t == 1) ? Bsl : Bsh;
            uint32_t abase = (uint32_t)__cvta_generic_to_shared(Asm);
            uint32_t bbase = (uint32_t)__cvta_generic_to_shared(Bsm);
            #pragma unroll
            for (int ks = 0; ks < 2; ks++) {
                int k0 = ks * 16;
                int lr = (lane & 7) + 8 * ((lane >> 3) & 1);
                int lc = 8 * (lane >> 4);
                uint32_t a[4][4];
                #pragma unroll
                for (int mi = 0; mi < 4; mi++) {
                    uint32_t addr = abase +
                        (uint32_t)(((warp_m + mi * 16 + lr) * APITCH + k0 + lc) * 2);
                    ldsm4(a[mi][0], a[mi][1], a[mi][2], a[mi][3], addr);
                }
                uint32_t b[4][2];
                #pragma unroll
                for (int njp = 0; njp < 2; njp++) {
                    uint32_t addr = bbase +
                        (uint32_t)(((k0 + lr) * BPITCH + warp_n + njp * 16 + lc) * 2);
                    uint32_t r0, r1, r2, r3;
                    ldsm4t(r0, r1, r2, r3, addr);
                    b[2 * njp][0] = r0;     b[2 * njp][1] = r1;
                    b[2 * njp + 1][0] = r2; b[2 * njp + 1][1] = r3;
                }
                #pragma unroll
                for (int mi = 0; mi < 4; mi++)
                    #pragma unroll
                    for (int nj = 0; nj < 4; nj++)
                        mma_bf16(c[mi][nj], a[mi], b[nj]);
            }
        }
        __syncthreads();
    }

    // epilogue
    #pragma unroll
    for (int mi = 0; mi < 4; mi++) {
        #pragma unroll
        for (int nj = 0; nj < 4; nj++) {
            int row0 = m0 + warp_m + mi * 16 + (lane >> 2);
            int col  = warp_n + nj * 8 + (lane & 3) * 2;
            float b0 = bias ? bias[col] : 0.f;
            float b1 = bias ? bias[col + 1] : 0.f;
            #pragma unroll
            for (int h = 0; h < 2; h++) {
                int row = row0 + 8 * h;
                if (row < M) {
                    float v0 = c[mi][nj][2 * h]     + b0;
                    float v1 = c[mi][nj][2 * h + 1] + b1;
                    if (outf) {
                        outf[row * D + col]     = v0;
                        outf[row * D + col + 1] = v1;
                    }
                    if (outh) {
                        bf16 h0, l0, h1, l1;
                        split_bf16(v0, h0, l0); split_bf16(v1, h1, l1);
                        *(bf162*)&outh[row * D + col] = __halves2bfloat162(h0, h1);
                        *(bf162*)&outl[row * D + col] = __halves2bfloat162(l0, l1);
                    }
                }
            }
        }
    }
}

// ---------------- edge scoring ---------------------------------------------
__global__ void k_edge(const int* __restrict__ s1, const int* __restrict__ d1,
                       const int* __restrict__ s2, const int* __restrict__ d2,
                       const float* __restrict__ Wp2, const float* __restrict__ bp2,
                       float* __restrict__ out)
{
    int gw   = (blockIdx.x * blockDim.x + threadIdx.x) >> 5;
    int lane = threadIdx.x & 31;
    if (gw >= 2 * N_EDGES) return;
    int ss, dd;
    if (gw < N_EDGES) { ss = s1[gw]; dd = d1[gw]; }
    else              { ss = s2[gw - N_EDGES]; dd = d2[gw - N_EDGES]; }

    float4 a = *(const float4*)&g_pa[ss * D + lane * 4];
    float4 b = *(const float4*)&g_pb[dd * D + lane * 4];
    float4 w = *(const float4*)&Wp2[lane * 4];

    float p = fmaxf(a.x + b.x, 0.f) * w.x
            + fmaxf(a.y + b.y, 0.f) * w.y
            + fmaxf(a.z + b.z, 0.f) * w.z
            + fmaxf(a.w + b.w, 0.f) * w.w;
    #pragma unroll
    for (int o = 16; o > 0; o >>= 1) p += __shfl_xor_sync(0xffffffffu, p, o);
    if (lane == 0) out[gw] = p + bp2[0];
}

// ---------------- launch ----------------------------------------------------
extern "C" void kernel_launch(void* const* d_in, const int* in_sizes, int n_in,
                              void* d_out, int out_size)
{
    const float* x    = (const float*)d_in[0];
    const int*   src  = (const int*)d_in[1];
    const int*   dst  = (const int*)d_in[2];
    const int*   nsrc = (const int*)d_in[3];
    const int*   ndst = (const int*)d_in[4];
    const float* Ws1 = (const float*)d_in[5],  *Wn1 = (const float*)d_in[6],  *b1 = (const float*)d_in[7];
    const float* Ws2 = (const float*)d_in[8],  *Wn2 = (const float*)d_in[9],  *b2 = (const float*)d_in[10];
    const float* Ws3 = (const float*)d_in[11], *Wn3 = (const float*)d_in[12], *b3 = (const float*)d_in[13];
    const float* Wp1 = (const float*)d_in[14], *bp1 = (const float*)d_in[15];
    const float* Wp2 = (const float*)d_in[16], *bp2 = (const float*)d_in[17];
    float* out = (float*)d_out;

    float *p_hA, *p_hB, *p_pa, *p_pb;
    bf16 *p_xbh, *p_xbl, *p_mbh, *p_mbl, *p_h1h, *p_h1l, *p_h2h, *p_h2l, *p_wh, *p_wl;
    cudaGetSymbolAddress((void**)&p_hA, g_hA);
    cudaGetSymbolAddress((void**)&p_hB, g_hB);
    cudaGetSymbolAddress((void**)&p_pa, g_pa);
    cudaGetSymbolAddress((void**)&p_pb, g_pb);
    cudaGetSymbolAddress((void**)&p_xbh, g_xbh);
    cudaGetSymbolAddress((void**)&p_xbl, g_xbl);
    cudaGetSymbolAddress((void**)&p_mbh, g_mbh);
    cudaGetSymbolAddress((void**)&p_mbl, g_mbl);
    cudaGetSymbolAddress((void**)&p_h1h, g_h1h);
    cudaGetSymbolAddress((void**)&p_h1l, g_h1l);
    cudaGetSymbolAddress((void**)&p_h2h, g_h2h);
    cudaGetSymbolAddress((void**)&p_h2l, g_h2l);
    cudaGetSymbolAddress((void**)&p_wh, g_wh);
    cudaGetSymbolAddress((void**)&p_wl, g_wl);

    // --- build CSR ---
    k_zero_cnt<<<(N_NODES + 255) / 256, 256>>>();
    k_hist<<<(N_EDGES + 255) / 256, 256>>>(dst);
    k_blockreduce<<<NB_SCAN, 1024>>>();
    k_scan_bsum<<<1, 32>>>();
    k_blockscan<<<NB_SCAN, 1024>>>();
    k_zero_cnt<<<(N_NODES + 255) / 256, 256>>>();
    k_place<<<(N_EDGES + 255) / 256, 256>>>(src, dst);

    // --- conversions ---
    int n4 = N_NODES * D / 4;
    k_cvt4<<<(n4 + 255) / 256, 256>>>(x, p_xbh, p_xbl, n4);
    k_cvt_w<<<(1024 * D + 255) / 256, 256>>>(Ws1, Wn1, Ws2, Wn2, Ws3, Wn3, Wp1);

    const int aggBlocks  = (N_NODES * 32 + 255) / 256;
    const int gemmBlocks = (N_NODES + 127) / 128;

    // --- layer 1 ---
    k_agg<<<aggBlocks, 256>>>(x);
    k_gemm_tc<<<gemmBlocks, 256>>>(p_xbh, p_xbl, p_mbh, p_mbl,
                                   p_wh, p_wl, b1, p_hA, p_h1h, p_h1l, N_NODES, 256);
    // --- layer 2 ---
    k_agg<<<aggBlocks, 256>>>(p_hA);
    k_gemm_tc<<<gemmBlocks, 256>>>(p_h1h, p_h1l, p_mbh, p_mbl,
                                   p_wh + 256 * D, p_wl + 256 * D, b2, p_hB, p_h2h, p_h2l, N_NODES, 256);
    // --- layer 3 (fp32 h not needed; only bf16 pair for predictor) ---
    k_agg<<<aggBlocks, 256>>>(p_hB);
    k_gemm_tc<<<gemmBlocks, 256>>>(p_h2h, p_h2l, p_mbh, p_mbl,
                                   p_wh + 512 * D, p_wl + 512 * D, b3, nullptr, p_h1h, p_h1l, N_NODES, 256);

    // --- predictor projections ---
    k_gemm_tc<<<gemmBlocks, 256>>>(p_h1h, p_h1l, nullptr, nullptr,
                                   p_wh + 768 * D, p_wl + 768 * D, bp1, p_pa, nullptr, nullptr, N_NODES, 128);
    k_gemm_tc<<<gemmBlocks, 256>>>(p_h1h, p_h1l, nullptr, nullptr,
                                   p_wh + 896 * D, p_wl + 896 * D, nullptr, p_pb, nullptr, nullptr, N_NODES, 128);

    // --- edge scores ---
    k_edge<<<(2 * N_EDGES * 32 + 255) / 256, 256>>>(src, dst, nsrc, ndst, Wp2, bp2, out);
}

// round 4
// speedup vs baseline: 1.6639x; 1.2626x over previous
#include <cuda_runtime.h>
#include <cuda_bf16.h>
#include <cstdint>

#define N_NODES 100000
#define N_EDGES 640000
#define D 128
#define NB_SCAN ((N_NODES + 1023) / 1024)   // 98

typedef __nv_bfloat16 bf16;
typedef __nv_bfloat162 bf162;

// ---------------- scratch (device globals: no allocation allowed) ----------
__device__ __align__(16) float g_hA[N_NODES * D];
__device__ __align__(16) float g_hB[N_NODES * D];
__device__ __align__(16) float g_pa[N_NODES * D];
__device__ __align__(16) float g_pb[N_NODES * D];
__device__ __align__(16) bf16 g_xbh[N_NODES * D];
__device__ __align__(16) bf16 g_xbl[N_NODES * D];
__device__ __align__(16) bf16 g_mbh[N_NODES * D];
__device__ __align__(16) bf16 g_mbl[N_NODES * D];
__device__ __align__(16) bf16 g_h1h[N_NODES * D];
__device__ __align__(16) bf16 g_h1l[N_NODES * D];
__device__ __align__(16) bf16 g_h2h[N_NODES * D];
__device__ __align__(16) bf16 g_h2l[N_NODES * D];
// packed weights rows [Ws1|Wn1|Ws2|Wn2|Ws3|Wn3|Wp1(256 rows)] = 1024 x 128, [K][N]
__device__ __align__(16) bf16 g_wh[1024 * D];
__device__ __align__(16) bf16 g_wl[1024 * D];
// CSR
__device__ int g_cnt[N_NODES];
__device__ int g_rowptr[N_NODES + 1];
__device__ int g_csr[N_EDGES];
__device__ int g_bsum[NB_SCAN];
__device__ int g_boff[NB_SCAN];

// ---------------- CSR construction ----------------------------------------
__global__ void k_zero_cnt() {
    int i = blockIdx.x * blockDim.x + threadIdx.x;
    if (i < N_NODES) g_cnt[i] = 0;
}
__global__ void k_hist(const int* __restrict__ dst) {
    int e = blockIdx.x * blockDim.x + threadIdx.x;
    if (e < N_EDGES) atomicAdd(&g_cnt[dst[e]], 1);
}
__global__ void k_blockreduce() {
    __shared__ int sh[1024];
    int i = blockIdx.x * 1024 + threadIdx.x;
    sh[threadIdx.x] = (i < N_NODES) ? g_cnt[i] : 0;
    __syncthreads();
    for (int o = 512; o > 0; o >>= 1) {
        if (threadIdx.x < o) sh[threadIdx.x] += sh[threadIdx.x + o];
        __syncthreads();
    }
    if (threadIdx.x == 0) g_bsum[blockIdx.x] = sh[0];
}
__global__ void k_scan_bsum() {
    if (threadIdx.x == 0 && blockIdx.x == 0) {
        int run = 0;
        for (int b = 0; b < NB_SCAN; b++) { g_boff[b] = run; run += g_bsum[b]; }
        g_rowptr[N_NODES] = run;
    }
}
__global__ void k_blockscan() {
    __shared__ int sh[1024];
    int tid = threadIdx.x;
    int i = blockIdx.x * 1024 + tid;
    int v = (i < N_NODES) ? g_cnt[i] : 0;
    sh[tid] = v;
    __syncthreads();
    for (int o = 1; o < 1024; o <<= 1) {
        int t = (tid >= o) ? sh[tid - o] : 0;
        __syncthreads();
        sh[tid] += t;
        __syncthreads();
    }
    if (i < N_NODES) g_rowptr[i] = g_boff[blockIdx.x] + sh[tid] - v;
}
__global__ void k_place(const int* __restrict__ src, const int* __restrict__ dst) {
    int e = blockIdx.x * blockDim.x + threadIdx.x;
    if (e < N_EDGES) {
        int d = dst[e];
        int slot = g_rowptr[d] + atomicAdd(&g_cnt[d], 1);
        g_csr[slot] = src[e];
    }
}

// ---------------- conversions ----------------------------------------------
__device__ __forceinline__ void split_bf16(float v, bf16& h, bf16& l) {
    h = __float2bfloat16_rn(v);
    l = __float2bfloat16_rn(v - __bfloat162float(h));
}

__global__ void k_cvt4(const float* __restrict__ in, bf16* __restrict__ oh,
                       bf16* __restrict__ ol, int n4) {
    int i = blockIdx.x * blockDim.x + threadIdx.x;
    if (i >= n4) return;
    float4 v = ((const float4*)in)[i];
    bf16 hx, hy, hz, hw, lx, ly, lz, lw;
    split_bf16(v.x, hx, lx); split_bf16(v.y, hy, ly);
    split_bf16(v.z, hz, lz); split_bf16(v.w, hw, lw);
    bf162* ph = (bf162*)&oh[i * 4];
    bf162* pl = (bf162*)&ol[i * 4];
    ph[0] = __halves2bfloat162(hx, hy); ph[1] = __halves2bfloat162(hz, hw);
    pl[0] = __halves2bfloat162(lx, ly); pl[1] = __halves2bfloat162(lz, lw);
}

__global__ void k_cvt_w(const float* Ws1, const float* Wn1,
                        const float* Ws2, const float* Wn2,
                        const float* Ws3, const float* Wn3,
                        const float* Wp1) {
    int i = blockIdx.x * blockDim.x + threadIdx.x;   // 0 .. 1024*128-1
    if (i >= 1024 * D) return;
    int row = i >> 7, col = i & 127;
    const float* s; int lr;
    if      (row < 128)  { s = Ws1; lr = row; }
    else if (row < 256)  { s = Wn1; lr = row - 128; }
    else if (row < 384)  { s = Ws2; lr = row - 256; }
    else if (row < 512)  { s = Wn2; lr = row - 384; }
    else if (row < 640)  { s = Ws3; lr = row - 512; }
    else if (row < 768)  { s = Wn3; lr = row - 640; }
    else                 { s = Wp1; lr = row - 768; }
    float v = s[lr * D + col];
    bf16 h, l; split_bf16(v, h, l);
    g_wh[i] = h; g_wl[i] = l;
}

// ---------------- mean aggregation (gather, warp-per-node) -> bf16 pair ----
__global__ void k_agg(const float* __restrict__ xin) {
    int gw   = (blockIdx.x * blockDim.x + threadIdx.x) >> 5;
    int lane = threadIdx.x & 31;
    if (gw >= N_NODES) return;
    int beg = g_rowptr[gw], end = g_rowptr[gw + 1];
    float4 acc = make_float4(0.f, 0.f, 0.f, 0.f);
    for (int e = beg; e < end; e++) {
        int s = g_csr[e];
        float4 v = *(const float4*)&xin[s * D + lane * 4];
        acc.x += v.x; acc.y += v.y; acc.z += v.z; acc.w += v.w;
    }
    int deg = end - beg;
    float inv = 1.0f / (float)(deg > 1 ? deg : 1);
    acc.x *= inv; acc.y *= inv; acc.z *= inv; acc.w *= inv;
    bf16 hx, hy, hz, hw, lx, ly, lz, lw;
    split_bf16(acc.x, hx, lx); split_bf16(acc.y, hy, ly);
    split_bf16(acc.z, hz, lz); split_bf16(acc.w, hw, lw);
    int idx = gw * D + lane * 4;
    bf162* ph = (bf162*)&g_mbh[idx];
    bf162* pl = (bf162*)&g_mbl[idx];
    ph[0] = __halves2bfloat162(hx, hy); ph[1] = __halves2bfloat162(hz, hw);
    pl[0] = __halves2bfloat162(lx, ly); pl[1] = __halves2bfloat162(lz, lw);
}

// ---------------- tensor-core GEMM (mma.sync, pipelined) -------------------
__device__ __forceinline__ void ldsm4(uint32_t& r0, uint32_t& r1, uint32_t& r2,
                                      uint32_t& r3, uint32_t addr) {
    asm volatile("ldmatrix.sync.aligned.m8n8.x4.shared.b16 {%0,%1,%2,%3}, [%4];"
                 : "=r"(r0), "=r"(r1), "=r"(r2), "=r"(r3) : "r"(addr));
}
__device__ __forceinline__ void ldsm4t(uint32_t& r0, uint32_t& r1, uint32_t& r2,
                                       uint32_t& r3, uint32_t addr) {
    asm volatile("ldmatrix.sync.aligned.m8n8.x4.trans.shared.b16 {%0,%1,%2,%3}, [%4];"
                 : "=r"(r0), "=r"(r1), "=r"(r2), "=r"(r3) : "r"(addr));
}
__device__ __forceinline__ void mma_bf16(float* c, const uint32_t* a, const uint32_t* b) {
    asm volatile(
        "mma.sync.aligned.m16n8k16.row.col.f32.bf16.bf16.f32 "
        "{%0,%1,%2,%3},{%4,%5,%6,%7},{%8,%9},{%0,%1,%2,%3};"
        : "+f"(c[0]), "+f"(c[1]), "+f"(c[2]), "+f"(c[3])
        : "r"(a[0]), "r"(a[1]), "r"(a[2]), "r"(a[3]), "r"(b[0]), "r"(b[1]));
}
__device__ __forceinline__ void cp16(uint32_t s, const void* g, bool p) {
    asm volatile("cp.async.cg.shared.global [%0], [%1], 16, %2;"
                 :: "r"(s), "l"(g), "r"(p ? 16 : 0));
}

#define A_STRIDE 80u        // bytes per A smem row (32 bf16 + pad)
#define B_STRIDE 272u       // bytes per B smem row (128 bf16 + pad)
#define A_BYTES (128u * A_STRIDE)   // 10240
#define B_BYTES (32u * B_STRIDE)    // 8704
#define STAGE (2u * A_BYTES + 2u * B_BYTES)  // 37888
#define GEMM_SMEM (2 * STAGE)                 // 75776

// out[M,128] = (A1|A2)[M,K] @ W[K,128] + bias ; 3-term bf16 split.
__global__ __launch_bounds__(256, 1) void k_gemm_tc(
    const bf16* __restrict__ A1h, const bf16* __restrict__ A1l,
    const bf16* __restrict__ A2h, const bf16* __restrict__ A2l,
    const bf16* __restrict__ Wh,  const bf16* __restrict__ Wl,
    const float* __restrict__ bias,
    float* __restrict__ outf,
    bf16* __restrict__ outh, bf16* __restrict__ outl,
    int M, int K)
{
    extern __shared__ char sm[];
    uint32_t base = (uint32_t)__cvta_generic_to_shared(sm);

    int tid = threadIdx.x;
    int wid = tid >> 5, lane = tid & 31;
    int warp_m = (wid >> 2) * 64;
    int warp_n = (wid & 3) * 32;
    int m0 = blockIdx.x * 128;
    int nch = K / 32;

    float c[4][4][4];
    #pragma unroll
    for (int i = 0; i < 4; i++)
        #pragma unroll
        for (int j = 0; j < 4; j++)
            #pragma unroll
            for (int q = 0; q < 4; q++) c[i][j][q] = 0.f;

    auto load_chunk = [&](int ch) {
        uint32_t st = base + (uint32_t)(ch & 1) * STAGE;
        int kb = ch * 32;
        const bf16* Ah = (kb < 128) ? A1h : A2h;
        const bf16* Al = (kb < 128) ? A1l : A2l;
        int ac = kb & 127;
        #pragma unroll
        for (int l = tid; l < 512; l += 256) {      // A: 128 rows x 4 segs
            int r = l >> 2, seg = l & 3;
            uint32_t so = (uint32_t)r * A_STRIDE + (uint32_t)seg * 16u;
            bool p = (m0 + r) < M;
            int rr = p ? (m0 + r) : 0;
            size_t go = (size_t)rr * D + ac + seg * 8;
            cp16(st + so,           Ah + go, p);
            cp16(st + A_BYTES + so, Al + go, p);
        }
        #pragma unroll
        for (int l = tid; l < 512; l += 256) {      // B: 32 rows x 16 segs
            int r = l >> 4, seg = l & 15;
            uint32_t so = (uint32_t)r * B_STRIDE + (uint32_t)seg * 16u;
            size_t go = (size_t)(kb + r) * D + seg * 8;
            cp16(st + 2u * A_BYTES + so,           Wh + go, true);
            cp16(st + 2u * A_BYTES + B_BYTES + so, Wl + go, true);
        }
        asm volatile("cp.async.commit_group;" ::: "memory");
    };

    load_chunk(0);

    int lr = (lane & 7) + 8 * ((lane >> 3) & 1);
    int lc = 8 * (lane >> 4);

    for (int ch = 0; ch < nch; ch++) {
        if (ch + 1 < nch) {
            load_chunk(ch + 1);
            asm volatile("cp.async.wait_group 1;" ::: "memory");
        } else {
            asm volatile("cp.async.wait_group 0;" ::: "memory");
        }
        __syncthreads();

        uint32_t st   = base + (uint32_t)(ch & 1) * STAGE;
        uint32_t ah_b = st;
        uint32_t al_b = st + A_BYTES;
        uint32_t bh_b = st + 2u * A_BYTES;
        uint32_t bl_b = bh_b + B_BYTES;

        #pragma unroll
        for (int ks = 0; ks < 2; ks++) {
            int k0 = ks * 16;
            uint32_t ah[4][4], al_[4][4];
            #pragma unroll
            for (int mi = 0; mi < 4; mi++) {
                uint32_t ro = (uint32_t)(warp_m + mi * 16 + lr) * A_STRIDE
                            + (uint32_t)(k0 + lc) * 2u;
                ldsm4(ah[mi][0], ah[mi][1], ah[mi][2], ah[mi][3], ah_b + ro);
                ldsm4(al_[mi][0], al_[mi][1], al_[mi][2], al_[mi][3], al_b + ro);
            }
            uint32_t bh[4][2], bl[4][2];
            #pragma unroll
            for (int njp = 0; njp < 2; njp++) {
                uint32_t ro = (uint32_t)(k0 + lr) * B_STRIDE
                            + (uint32_t)(warp_n + njp * 16 + lc) * 2u;
                uint32_t r0, r1, r2, r3;
                ldsm4t(r0, r1, r2, r3, bh_b + ro);
                bh[2 * njp][0] = r0;     bh[2 * njp][1] = r1;
                bh[2 * njp + 1][0] = r2; bh[2 * njp + 1][1] = r3;
                ldsm4t(r0, r1, r2, r3, bl_b + ro);
                bl[2 * njp][0] = r0;     bl[2 * njp][1] = r1;
                bl[2 * njp + 1][0] = r2; bl[2 * njp + 1][1] = r3;
            }
            #pragma unroll
            for (int mi = 0; mi < 4; mi++)
                #pragma unroll
                for (int nj = 0; nj < 4; nj++) {
                    mma_bf16(c[mi][nj], ah[mi], bh[nj]);
                    mma_bf16(c[mi][nj], ah[mi], bl[nj]);
                    mma_bf16(c[mi][nj], al_[mi], bh[nj]);
                }
        }
        __syncthreads();
    }

    // epilogue
    #pragma unroll
    for (int mi = 0; mi < 4; mi++) {
        #pragma unroll
        for (int nj = 0; nj < 4; nj++) {
            int row0 = m0 + warp_m + mi * 16 + (lane >> 2);
            int col  = warp_n + nj * 8 + (lane & 3) * 2;
            float b0 = bias ? bias[col] : 0.f;
            float b1 = bias ? bias[col + 1] : 0.f;
            #pragma unroll
            for (int h = 0; h < 2; h++) {
                int row = row0 + 8 * h;
                if (row < M) {
                    float v0 = c[mi][nj][2 * h]     + b0;
                    float v1 = c[mi][nj][2 * h + 1] + b1;
                    if (outf) {
                        outf[(size_t)row * D + col]     = v0;
                        outf[(size_t)row * D + col + 1] = v1;
                    }
                    if (outh) {
                        bf16 h0, l0, h1, l1;
                        split_bf16(v0, h0, l0); split_bf16(v1, h1, l1);
                        *(bf162*)&outh[(size_t)row * D + col] = __halves2bfloat162(h0, h1);
                        *(bf162*)&outl[(size_t)row * D + col] = __halves2bfloat162(l0, l1);
                    }
                }
            }
        }
    }
}

// ---------------- edge scoring ---------------------------------------------
__global__ void k_edge(const int* __restrict__ s1, const int* __restrict__ d1,
                       const int* __restrict__ s2, const int* __restrict__ d2,
                       const float* __restrict__ Wp2, const float* __restrict__ bp2,
                       float* __restrict__ out)
{
    int gw   = (blockIdx.x * blockDim.x + threadIdx.x) >> 5;
    int lane = threadIdx.x & 31;
    if (gw >= 2 * N_EDGES) return;
    int ss, dd;
    if (gw < N_EDGES) { ss = s1[gw]; dd = d1[gw]; }
    else              { ss = s2[gw - N_EDGES]; dd = d2[gw - N_EDGES]; }

    float4 a = *(const float4*)&g_pa[ss * D + lane * 4];
    float4 b = *(const float4*)&g_pb[dd * D + lane * 4];
    float4 w = *(const float4*)&Wp2[lane * 4];

    float p = fmaxf(a.x + b.x, 0.f) * w.x
            + fmaxf(a.y + b.y, 0.f) * w.y
            + fmaxf(a.z + b.z, 0.f) * w.z
            + fmaxf(a.w + b.w, 0.f) * w.w;
    #pragma unroll
    for (int o = 16; o > 0; o >>= 1) p += __shfl_xor_sync(0xffffffffu, p, o);
    if (lane == 0) out[gw] = p + bp2[0];
}

// ---------------- launch ----------------------------------------------------
extern "C" void kernel_launch(void* const* d_in, const int* in_sizes, int n_in,
                              void* d_out, int out_size)
{
    const float* x    = (const float*)d_in[0];
    const int*   src  = (const int*)d_in[1];
    const int*   dst  = (const int*)d_in[2];
    const int*   nsrc = (const int*)d_in[3];
    const int*   ndst = (const int*)d_in[4];
    const float* Ws1 = (const float*)d_in[5],  *Wn1 = (const float*)d_in[6],  *b1 = (const float*)d_in[7];
    const float* Ws2 = (const float*)d_in[8],  *Wn2 = (const float*)d_in[9],  *b2 = (const float*)d_in[10];
    const float* Ws3 = (const float*)d_in[11], *Wn3 = (const float*)d_in[12], *b3 = (const float*)d_in[13];
    const float* Wp1 = (const float*)d_in[14], *bp1 = (const float*)d_in[15];
    const float* Wp2 = (const float*)d_in[16], *bp2 = (const float*)d_in[17];
    float* out = (float*)d_out;

    float *p_hA, *p_hB, *p_pa, *p_pb;
    bf16 *p_xbh, *p_xbl, *p_mbh, *p_mbl, *p_h1h, *p_h1l, *p_h2h, *p_h2l, *p_wh, *p_wl;
    cudaGetSymbolAddress((void**)&p_hA, g_hA);
    cudaGetSymbolAddress((void**)&p_hB, g_hB);
    cudaGetSymbolAddress((void**)&p_pa, g_pa);
    cudaGetSymbolAddress((void**)&p_pb, g_pb);
    cudaGetSymbolAddress((void**)&p_xbh, g_xbh);
    cudaGetSymbolAddress((void**)&p_xbl, g_xbl);
    cudaGetSymbolAddress((void**)&p_mbh, g_mbh);
    cudaGetSymbolAddress((void**)&p_mbl, g_mbl);
    cudaGetSymbolAddress((void**)&p_h1h, g_h1h);
    cudaGetSymbolAddress((void**)&p_h1l, g_h1l);
    cudaGetSymbolAddress((void**)&p_h2h, g_h2h);
    cudaGetSymbolAddress((void**)&p_h2l, g_h2l);
    cudaGetSymbolAddress((void**)&p_wh, g_wh);
    cudaGetSymbolAddress((void**)&p_wl, g_wl);

    cudaFuncSetAttribute(k_gemm_tc, cudaFuncAttributeMaxDynamicSharedMemorySize,
                         GEMM_SMEM);

    // --- build CSR ---
    k_zero_cnt<<<(N_NODES + 255) / 256, 256>>>();
    k_hist<<<(N_EDGES + 255) / 256, 256>>>(dst);
    k_blockreduce<<<NB_SCAN, 1024>>>();
    k_scan_bsum<<<1, 32>>>();
    k_blockscan<<<NB_SCAN, 1024>>>();
    k_zero_cnt<<<(N_NODES + 255) / 256, 256>>>();
    k_place<<<(N_EDGES + 255) / 256, 256>>>(src, dst);

    // --- conversions ---
    int n4 = N_NODES * D / 4;
    k_cvt4<<<(n4 + 255) / 256, 256>>>(x, p_xbh, p_xbl, n4);
    k_cvt_w<<<(1024 * D + 255) / 256, 256>>>(Ws1, Wn1, Ws2, Wn2, Ws3, Wn3, Wp1);

    const int aggBlocks  = (N_NODES * 32 + 255) / 256;
    const int gemmBlocks = (N_NODES + 127) / 128;

    // --- layer 1 ---
    k_agg<<<aggBlocks, 256>>>(x);
    k_gemm_tc<<<gemmBlocks, 256, GEMM_SMEM>>>(p_xbh, p_xbl, p_mbh, p_mbl,
                                   p_wh, p_wl, b1, p_hA, p_h1h, p_h1l, N_NODES, 256);
    // --- layer 2 ---
    k_agg<<<aggBlocks, 256>>>(p_hA);
    k_gemm_tc<<<gemmBlocks, 256, GEMM_SMEM>>>(p_h1h, p_h1l, p_mbh, p_mbl,
                                   p_wh + 256 * D, p_wl + 256 * D, b2, p_hB, p_h2h, p_h2l, N_NODES, 256);
    // --- layer 3 ---
    k_agg<<<aggBlocks, 256>>>(p_hB);
    k_gemm_tc<<<gemmBlocks, 256, GEMM_SMEM>>>(p_h2h, p_h2l, p_mbh, p_mbl,
                                   p_wh + 512 * D, p_wl + 512 * D, b3, nullptr, p_h1h, p_h1l, N_NODES, 256);

    // --- predictor projections ---
    k_gemm_tc<<<gemmBlocks, 256, GEMM_SMEM>>>(p_h1h, p_h1l, nullptr, nullptr,
                                   p_wh + 768 * D, p_wl + 768 * D, bp1, p_pa, nullptr, nullptr, N_NODES, 128);
    k_gemm_tc<<<gemmBlocks, 256, GEMM_SMEM>>>(p_h1h, p_h1l, nullptr, nullptr,
                                   p_wh + 896 * D, p_wl + 896 * D, nullptr, p_pb, nullptr, nullptr, N_NODES, 128);

    // --- edge scores ---
    k_edge<<<(2 * N_EDGES * 32 + 255) / 256, 256>>>(src, dst, nsrc, ndst, Wp2, bp2, out);
}

// round 5
// speedup vs baseline: 1.7954x; 1.0790x over previous
#include <cuda_runtime.h>
#include <cuda_bf16.h>
#include <cuda_fp16.h>
#include <cstdint>

#define N_NODES 100000
#define N_EDGES 640000
#define D 128
#define NB_SCAN ((N_NODES + 1023) / 1024)   // 98

typedef __nv_bfloat16 bf16;
typedef __nv_bfloat162 bf162;

// ---------------- scratch (device globals: no allocation allowed) ----------
__device__ __align__(16) __half g_pa16[N_NODES * D];
__device__ __align__(16) __half g_pb16[N_NODES * D];
__device__ __align__(16) bf16 g_xbh[N_NODES * D];
__device__ __align__(16) bf16 g_xbl[N_NODES * D];
__device__ __align__(16) bf16 g_mbh[N_NODES * D];
__device__ __align__(16) bf16 g_mbl[N_NODES * D];
__device__ __align__(16) bf16 g_h1h[N_NODES * D];
__device__ __align__(16) bf16 g_h1l[N_NODES * D];
__device__ __align__(16) bf16 g_h2h[N_NODES * D];
__device__ __align__(16) bf16 g_h2l[N_NODES * D];
// packed weights rows [Ws1|Wn1|Ws2|Wn2|Ws3|Wn3|Wp1(256 rows)] = 1024 x 128, [K][N]
__device__ __align__(16) bf16 g_wh[1024 * D];
__device__ __align__(16) bf16 g_wl[1024 * D];
// CSR
__device__ int g_cnt[N_NODES];
__device__ int g_rowptr[N_NODES + 1];
__device__ int g_csr[N_EDGES];
__device__ int g_bsum[NB_SCAN];
__device__ int g_boff[NB_SCAN];

// ---------------- CSR construction ----------------------------------------
__global__ void k_zero_cnt() {
    int i = blockIdx.x * blockDim.x + threadIdx.x;
    if (i < N_NODES) g_cnt[i] = 0;
}
__global__ void k_hist(const int* __restrict__ dst) {
    int e = blockIdx.x * blockDim.x + threadIdx.x;
    if (e < N_EDGES) atomicAdd(&g_cnt[dst[e]], 1);
}
__global__ void k_blockreduce() {
    __shared__ int sh[1024];
    int i = blockIdx.x * 1024 + threadIdx.x;
    sh[threadIdx.x] = (i < N_NODES) ? g_cnt[i] : 0;
    __syncthreads();
    for (int o = 512; o > 0; o >>= 1) {
        if (threadIdx.x < o) sh[threadIdx.x] += sh[threadIdx.x + o];
        __syncthreads();
    }
    if (threadIdx.x == 0) g_bsum[blockIdx.x] = sh[0];
}
__global__ void k_scan_bsum() {
    if (threadIdx.x == 0 && blockIdx.x == 0) {
        int run = 0;
        for (int b = 0; b < NB_SCAN; b++) { g_boff[b] = run; run += g_bsum[b]; }
        g_rowptr[N_NODES] = run;
    }
}
__global__ void k_blockscan() {
    __shared__ int sh[1024];
    int tid = threadIdx.x;
    int i = blockIdx.x * 1024 + tid;
    int v = (i < N_NODES) ? g_cnt[i] : 0;
    sh[tid] = v;
    __syncthreads();
    for (int o = 1; o < 1024; o <<= 1) {
        int t = (tid >= o) ? sh[tid - o] : 0;
        __syncthreads();
        sh[tid] += t;
        __syncthreads();
    }
    if (i < N_NODES) g_rowptr[i] = g_boff[blockIdx.x] + sh[tid] - v;
}
__global__ void k_place(const int* __restrict__ src, const int* __restrict__ dst) {
    int e = blockIdx.x * blockDim.x + threadIdx.x;
    if (e < N_EDGES) {
        int d = dst[e];
        int slot = g_rowptr[d] + atomicAdd(&g_cnt[d], 1);
        g_csr[slot] = src[e];
    }
}

// ---------------- conversions ----------------------------------------------
__device__ __forceinline__ void split_bf16(float v, bf16& h, bf16& l) {
    h = __float2bfloat16_rn(v);
    l = __float2bfloat16_rn(v - __bfloat162float(h));
}

__global__ void k_cvt4(const float* __restrict__ in, bf16* __restrict__ oh,
                       bf16* __restrict__ ol, int n4) {
    int i = blockIdx.x * blockDim.x + threadIdx.x;
    if (i >= n4) return;
    float4 v = ((const float4*)in)[i];
    bf16 hx, hy, hz, hw, lx, ly, lz, lw;
    split_bf16(v.x, hx, lx); split_bf16(v.y, hy, ly);
    split_bf16(v.z, hz, lz); split_bf16(v.w, hw, lw);
    bf162* ph = (bf162*)&oh[i * 4];
    bf162* pl = (bf162*)&ol[i * 4];
    ph[0] = __halves2bfloat162(hx, hy); ph[1] = __halves2bfloat162(hz, hw);
    pl[0] = __halves2bfloat162(lx, ly); pl[1] = __halves2bfloat162(lz, lw);
}

__global__ void k_cvt_w(const float* Ws1, const float* Wn1,
                        const float* Ws2, const float* Wn2,
                        const float* Ws3, const float* Wn3,
                        const float* Wp1) {
    int i = blockIdx.x * blockDim.x + threadIdx.x;   // 0 .. 1024*128-1
    if (i >= 1024 * D) return;
    int row = i >> 7, col = i & 127;
    const float* s; int lr;
    if      (row < 128)  { s = Ws1; lr = row; }
    else if (row < 256)  { s = Wn1; lr = row - 128; }
    else if (row < 384)  { s = Ws2; lr = row - 256; }
    else if (row < 512)  { s = Wn2; lr = row - 384; }
    else if (row < 640)  { s = Ws3; lr = row - 512; }
    else if (row < 768)  { s = Wn3; lr = row - 640; }
    else                 { s = Wp1; lr = row - 768; }
    float v = s[lr * D + col];
    bf16 h, l; split_bf16(v, h, l);
    g_wh[i] = h; g_wl[i] = l;
}

// ---------------- mean aggregation: reads bf16 hi/lo pair ------------------
__global__ void k_agg(const bf16* __restrict__ xh, const bf16* __restrict__ xl) {
    int gw   = (blockIdx.x * blockDim.x + threadIdx.x) >> 5;
    int lane = threadIdx.x & 31;
    if (gw >= N_NODES) return;
    int beg = g_rowptr[gw], end = g_rowptr[gw + 1];
    float4 acc = make_float4(0.f, 0.f, 0.f, 0.f);
    for (int e = beg; e < end; e++) {
        int idx = g_csr[e] * D + lane * 4;
        uint2 vh = *(const uint2*)&xh[idx];
        uint2 vl = *(const uint2*)&xl[idx];
        float2 h0 = __bfloat1622float2(*(bf162*)&vh.x);
        float2 h1 = __bfloat1622float2(*(bf162*)&vh.y);
        float2 l0 = __bfloat1622float2(*(bf162*)&vl.x);
        float2 l1 = __bfloat1622float2(*(bf162*)&vl.y);
        acc.x += h0.x + l0.x; acc.y += h0.y + l0.y;
        acc.z += h1.x + l1.x; acc.w += h1.y + l1.y;
    }
    int deg = end - beg;
    float inv = 1.0f / (float)(deg > 1 ? deg : 1);
    acc.x *= inv; acc.y *= inv; acc.z *= inv; acc.w *= inv;
    bf16 hx, hy, hz, hw, lx, ly, lz, lw;
    split_bf16(acc.x, hx, lx); split_bf16(acc.y, hy, ly);
    split_bf16(acc.z, hz, lz); split_bf16(acc.w, hw, lw);
    int idx = gw * D + lane * 4;
    bf162* ph = (bf162*)&g_mbh[idx];
    bf162* pl = (bf162*)&g_mbl[idx];
    ph[0] = __halves2bfloat162(hx, hy); ph[1] = __halves2bfloat162(hz, hw);
    pl[0] = __halves2bfloat162(lx, ly); pl[1] = __halves2bfloat162(lz, lw);
}

// ---------------- tensor-core GEMM (mma.sync, 3-stage pipeline) ------------
__device__ __forceinline__ void ldsm4(uint32_t& r0, uint32_t& r1, uint32_t& r2,
                                      uint32_t& r3, uint32_t addr) {
    asm volatile("ldmatrix.sync.aligned.m8n8.x4.shared.b16 {%0,%1,%2,%3}, [%4];"
                 : "=r"(r0), "=r"(r1), "=r"(r2), "=r"(r3) : "r"(addr));
}
__device__ __forceinline__ void ldsm4t(uint32_t& r0, uint32_t& r1, uint32_t& r2,
                                       uint32_t& r3, uint32_t addr) {
    asm volatile("ldmatrix.sync.aligned.m8n8.x4.trans.shared.b16 {%0,%1,%2,%3}, [%4];"
                 : "=r"(r0), "=r"(r1), "=r"(r2), "=r"(r3) : "r"(addr));
}
__device__ __forceinline__ void mma_bf16(float* c, const uint32_t* a, const uint32_t* b) {
    asm volatile(
        "mma.sync.aligned.m16n8k16.row.col.f32.bf16.bf16.f32 "
        "{%0,%1,%2,%3},{%4,%5,%6,%7},{%8,%9},{%0,%1,%2,%3};"
        : "+f"(c[0]), "+f"(c[1]), "+f"(c[2]), "+f"(c[3])
        : "r"(a[0]), "r"(a[1]), "r"(a[2]), "r"(a[3]), "r"(b[0]), "r"(b[1]));
}
__device__ __forceinline__ void cp16(uint32_t s, const void* g, bool p) {
    asm volatile("cp.async.cg.shared.global [%0], [%1], 16, %2;"
                 :: "r"(s), "l"(g), "r"(p ? 16 : 0));
}

#define A_STRIDE 80u        // bytes per A smem row (32 bf16 + pad)
#define B_STRIDE 272u       // bytes per B smem row (128 bf16 + pad)
#define A_BYTES (128u * A_STRIDE)   // 10240
#define B_BYTES (32u * B_STRIDE)    // 8704
#define STAGE (2u * A_BYTES + 2u * B_BYTES)  // 37888
#define GEMM_SMEM (3 * STAGE)                 // 113664

// out[M,128] = (A1|A2)[M,K] @ W[K,128] + bias ; 3-term bf16 split.
// If out16a set (predictor): gridDim.y==2 selects weight block / output.
__global__ __launch_bounds__(256, 1) void k_gemm_tc(
    const bf16* __restrict__ A1h, const bf16* __restrict__ A1l,
    const bf16* __restrict__ A2h, const bf16* __restrict__ A2l,
    const bf16* __restrict__ Wh,  const bf16* __restrict__ Wl,
    const float* __restrict__ bias,
    bf16* __restrict__ outh, bf16* __restrict__ outl,
    __half* __restrict__ out16a, __half* __restrict__ out16b,
    int M, int K)
{
    extern __shared__ char sm[];
    uint32_t base = (uint32_t)__cvta_generic_to_shared(sm);

    __half* o16 = out16a;
    if (out16a && blockIdx.y == 1) {
        Wh += 128 * D; Wl += 128 * D;
        o16 = out16b; bias = nullptr;
    }

    int tid = threadIdx.x;
    int wid = tid >> 5, lane = tid & 31;
    int warp_m = (wid >> 2) * 64;
    int warp_n = (wid & 3) * 32;
    int m0 = blockIdx.x * 128;
    int nch = K / 32;          // 4 or 8

    float c[4][4][4];
    #pragma unroll
    for (int i = 0; i < 4; i++)
        #pragma unroll
        for (int j = 0; j < 4; j++)
            #pragma unroll
            for (int q = 0; q < 4; q++) c[i][j][q] = 0.f;

    auto load_chunk = [&](int ch) {
        uint32_t st = base + (uint32_t)(ch % 3) * STAGE;
        int kb = ch * 32;
        const bf16* Ah = (kb < 128) ? A1h : A2h;
        const bf16* Al = (kb < 128) ? A1l : A2l;
        int ac = kb & 127;
        #pragma unroll
        for (int l = tid; l < 512; l += 256) {      // A: 128 rows x 4 segs
            int r = l >> 2, seg = l & 3;
            uint32_t so = (uint32_t)r * A_STRIDE + (uint32_t)seg * 16u;
            bool p = (m0 + r) < M;
            int rr = p ? (m0 + r) : 0;
            size_t go = (size_t)rr * D + ac + seg * 8;
            cp16(st + so,           Ah + go, p);
            cp16(st + A_BYTES + so, Al + go, p);
        }
        #pragma unroll
        for (int l = tid; l < 512; l += 256) {      // B: 32 rows x 16 segs
            int r = l >> 4, seg = l & 15;
            uint32_t so = (uint32_t)r * B_STRIDE + (uint32_t)seg * 16u;
            size_t go = (size_t)(kb + r) * D + seg * 8;
            cp16(st + 2u * A_BYTES + so,           Wh + go, true);
            cp16(st + 2u * A_BYTES + B_BYTES + so, Wl + go, true);
        }
        asm volatile("cp.async.commit_group;" ::: "memory");
    };

    load_chunk(0);
    load_chunk(1);

    int lr = (lane & 7) + 8 * ((lane >> 3) & 1);
    int lc = 8 * (lane >> 4);

    for (int ch = 0; ch < nch; ch++) {
        if (ch + 1 < nch) {
            asm volatile("cp.async.wait_group 1;" ::: "memory");
        } else {
            asm volatile("cp.async.wait_group 0;" ::: "memory");
        }
        __syncthreads();
        if (ch + 2 < nch) load_chunk(ch + 2);

        uint32_t st   = base + (uint32_t)(ch % 3) * STAGE;
        uint32_t ah_b = st;
        uint32_t al_b = st + A_BYTES;
        uint32_t bh_b = st + 2u * A_BYTES;
        uint32_t bl_b = bh_b + B_BYTES;

        #pragma unroll
        for (int ks = 0; ks < 2; ks++) {
            int k0 = ks * 16;
            uint32_t ah[4][4], al_[4][4];
            #pragma unroll
            for (int mi = 0; mi < 4; mi++) {
                uint32_t ro = (uint32_t)(warp_m + mi * 16 + lr) * A_STRIDE
                            + (uint32_t)(k0 + lc) * 2u;
                ldsm4(ah[mi][0], ah[mi][1], ah[mi][2], ah[mi][3], ah_b + ro);
                ldsm4(al_[mi][0], al_[mi][1], al_[mi][2], al_[mi][3], al_b + ro);
            }
            uint32_t bh[4][2], bl[4][2];
            #pragma unroll
            for (int njp = 0; njp < 2; njp++) {
                uint32_t ro = (uint32_t)(k0 + lr) * B_STRIDE
                            + (uint32_t)(warp_n + njp * 16 + lc) * 2u;
                uint32_t r0, r1, r2, r3;
                ldsm4t(r0, r1, r2, r3, bh_b + ro);
                bh[2 * njp][0] = r0;     bh[2 * njp][1] = r1;
                bh[2 * njp + 1][0] = r2; bh[2 * njp + 1][1] = r3;
                ldsm4t(r0, r1, r2, r3, bl_b + ro);
                bl[2 * njp][0] = r0;     bl[2 * njp][1] = r1;
                bl[2 * njp + 1][0] = r2; bl[2 * njp + 1][1] = r3;
            }
            #pragma unroll
            for (int mi = 0; mi < 4; mi++)
                #pragma unroll
                for (int nj = 0; nj < 4; nj++) {
                    mma_bf16(c[mi][nj], ah[mi], bh[nj]);
                    mma_bf16(c[mi][nj], ah[mi], bl[nj]);
                    mma_bf16(c[mi][nj], al_[mi], bh[nj]);
                }
        }
        __syncthreads();
    }

    // epilogue
    #pragma unroll
    for (int mi = 0; mi < 4; mi++) {
        #pragma unroll
        for (int nj = 0; nj < 4; nj++) {
            int row0 = m0 + warp_m + mi * 16 + (lane >> 2);
            int col  = warp_n + nj * 8 + (lane & 3) * 2;
            float b0 = bias ? bias[col] : 0.f;
            float b1 = bias ? bias[col + 1] : 0.f;
            #pragma unroll
            for (int h = 0; h < 2; h++) {
                int row = row0 + 8 * h;
                if (row < M) {
                    float v0 = c[mi][nj][2 * h]     + b0;
                    float v1 = c[mi][nj][2 * h + 1] + b1;
                    if (o16) {
                        *(__half2*)&o16[(size_t)row * D + col] =
                            __floats2half2_rn(v0, v1);
                    } else {
                        bf16 h0, l0, h1, l1;
                        split_bf16(v0, h0, l0); split_bf16(v1, h1, l1);
                        *(bf162*)&outh[(size_t)row * D + col] = __halves2bfloat162(h0, h1);
                        *(bf162*)&outl[(size_t)row * D + col] = __halves2bfloat162(l0, l1);
                    }
                }
            }
        }
    }
}

// ---------------- edge scoring (fp16 projections) ---------------------------
__global__ void k_edge(const int* __restrict__ s1, const int* __restrict__ d1,
                       const int* __restrict__ s2, const int* __restrict__ d2,
                       const float* __restrict__ Wp2, const float* __restrict__ bp2,
                       float* __restrict__ out)
{
    int gw   = (blockIdx.x * blockDim.x + threadIdx.x) >> 5;
    int lane = threadIdx.x & 31;
    if (gw >= 2 * N_EDGES) return;
    int ss, dd;
    if (gw < N_EDGES) { ss = s1[gw]; dd = d1[gw]; }
    else              { ss = s2[gw - N_EDGES]; dd = d2[gw - N_EDGES]; }

    uint2 av = *(const uint2*)&g_pa16[(size_t)ss * D + lane * 4];
    uint2 bv = *(const uint2*)&g_pb16[(size_t)dd * D + lane * 4];
    float2 a0 = __half22float2(*(__half2*)&av.x);
    float2 a1 = __half22float2(*(__half2*)&av.y);
    float2 b0 = __half22float2(*(__half2*)&bv.x);
    float2 b1 = __half22float2(*(__half2*)&bv.y);
    float4 w = *(const float4*)&Wp2[lane * 4];

    float p = fmaxf(a0.x + b0.x, 0.f) * w.x
            + fmaxf(a0.y + b0.y, 0.f) * w.y
            + fmaxf(a1.x + b1.x, 0.f) * w.z
            + fmaxf(a1.y + b1.y, 0.f) * w.w;
    #pragma unroll
    for (int o = 16; o > 0; o >>= 1) p += __shfl_xor_sync(0xffffffffu, p, o);
    if (lane == 0) out[gw] = p + bp2[0];
}

// ---------------- launch ----------------------------------------------------
extern "C" void kernel_launch(void* const* d_in, const int* in_sizes, int n_in,
                              void* d_out, int out_size)
{
    const float* x    = (const float*)d_in[0];
    const int*   src  = (const int*)d_in[1];
    const int*   dst  = (const int*)d_in[2];
    const int*   nsrc = (const int*)d_in[3];
    const int*   ndst = (const int*)d_in[4];
    const float* Ws1 = (const float*)d_in[5],  *Wn1 = (const float*)d_in[6],  *b1 = (const float*)d_in[7];
    const float* Ws2 = (const float*)d_in[8],  *Wn2 = (const float*)d_in[9],  *b2 = (const float*)d_in[10];
    const float* Ws3 = (const float*)d_in[11], *Wn3 = (const float*)d_in[12], *b3 = (const float*)d_in[13];
    const float* Wp1 = (const float*)d_in[14], *bp1 = (const float*)d_in[15];
    const float* Wp2 = (const float*)d_in[16], *bp2 = (const float*)d_in[17];
    float* out = (float*)d_out;

    __half *p_pa16, *p_pb16;
    bf16 *p_xbh, *p_xbl, *p_mbh, *p_mbl, *p_h1h, *p_h1l, *p_h2h, *p_h2l, *p_wh, *p_wl;
    cudaGetSymbolAddress((void**)&p_pa16, g_pa16);
    cudaGetSymbolAddress((void**)&p_pb16, g_pb16);
    cudaGetSymbolAddress((void**)&p_xbh, g_xbh);
    cudaGetSymbolAddress((void**)&p_xbl, g_xbl);
    cudaGetSymbolAddress((void**)&p_mbh, g_mbh);
    cudaGetSymbolAddress((void**)&p_mbl, g_mbl);
    cudaGetSymbolAddress((void**)&p_h1h, g_h1h);
    cudaGetSymbolAddress((void**)&p_h1l, g_h1l);
    cudaGetSymbolAddress((void**)&p_h2h, g_h2h);
    cudaGetSymbolAddress((void**)&p_h2l, g_h2l);
    cudaGetSymbolAddress((void**)&p_wh, g_wh);
    cudaGetSymbolAddress((void**)&p_wl, g_wl);

    cudaFuncSetAttribute(k_gemm_tc, cudaFuncAttributeMaxDynamicSharedMemorySize,
                         GEMM_SMEM);

    // --- build CSR ---
    k_zero_cnt<<<(N_NODES + 255) / 256, 256>>>();
    k_hist<<<(N_EDGES + 255) / 256, 256>>>(dst);
    k_blockreduce<<<NB_SCAN, 1024>>>();
    k_scan_bsum<<<1, 32>>>();
    k_blockscan<<<NB_SCAN, 1024>>>();
    k_zero_cnt<<<(N_NODES + 255) / 256, 256>>>();
    k_place<<<(N_EDGES + 255) / 256, 256>>>(src, dst);

    // --- conversions ---
    int n4 = N_NODES * D / 4;
    k_cvt4<<<(n4 + 255) / 256, 256>>>(x, p_xbh, p_xbl, n4);
    k_cvt_w<<<(1024 * D + 255) / 256, 256>>>(Ws1, Wn1, Ws2, Wn2, Ws3, Wn3, Wp1);

    const int aggBlocks  = (N_NODES * 32 + 255) / 256;
    const int gemmBlocks = (N_NODES + 127) / 128;

    // --- layer 1 ---
    k_agg<<<aggBlocks, 256>>>(p_xbh, p_xbl);
    k_gemm_tc<<<gemmBlocks, 256, GEMM_SMEM>>>(p_xbh, p_xbl, p_mbh, p_mbl,
                                   p_wh, p_wl, b1,
                                   p_h1h, p_h1l, nullptr, nullptr, N_NODES, 256);
    // --- layer 2 ---
    k_agg<<<aggBlocks, 256>>>(p_h1h, p_h1l);
    k_gemm_tc<<<gemmBlocks, 256, GEMM_SMEM>>>(p_h1h, p_h1l, p_mbh, p_mbl,
                                   p_wh + 256 * D, p_wl + 256 * D, b2,
                                   p_h2h, p_h2l, nullptr, nullptr, N_NODES, 256);
    // --- layer 3 (write into h1 pair, free at this point) ---
    k_agg<<<aggBlocks, 256>>>(p_h2h, p_h2l);
    k_gemm_tc<<<gemmBlocks, 256, GEMM_SMEM>>>(p_h2h, p_h2l, p_mbh, p_mbl,
                                   p_wh + 512 * D, p_wl + 512 * D, b3,
                                   p_h1h, p_h1l, nullptr, nullptr, N_NODES, 256);

    // --- predictor projections (merged: gridDim.y=2 -> pa, pb in fp16) ---
    k_gemm_tc<<<dim3(gemmBlocks, 2), 256, GEMM_SMEM>>>(
                                   p_h1h, p_h1l, nullptr, nullptr,
                                   p_wh + 768 * D, p_wl + 768 * D, bp1,
                                   nullptr, nullptr, p_pa16, p_pb16, N_NODES, 128);

    // --- edge scores ---
    k_edge<<<(2 * N_EDGES * 32 + 255) / 256, 256>>>(src, dst, nsrc, ndst, Wp2, bp2, out);
}

// round 6
// speedup vs baseline: 2.0528x; 1.1433x over previous
#include <cuda_runtime.h>
#include <cuda_bf16.h>
#include <cuda_fp16.h>
#include <cstdint>

#define N_NODES 100000
#define N_EDGES 640000
#define D 128
#define NB_SCAN ((N_NODES + 1023) / 1024)   // 98

typedef __nv_bfloat16 bf16;
typedef __nv_bfloat162 bf162;

// ---------------- scratch (device globals: no allocation allowed) ----------
__device__ __align__(16) __half g_pa16[N_NODES * D];
__device__ __align__(16) __half g_pb16[N_NODES * D];
__device__ __align__(16) bf16 g_xbh[N_NODES * D];
__device__ __align__(16) bf16 g_xbl[N_NODES * D];
__device__ __align__(16) bf16 g_mbh[N_NODES * D];
__device__ __align__(16) bf16 g_mbl[N_NODES * D];
__device__ __align__(16) bf16 g_h1h[N_NODES * D];
__device__ __align__(16) bf16 g_h1l[N_NODES * D];
__device__ __align__(16) bf16 g_h2h[N_NODES * D];
__device__ __align__(16) bf16 g_h2l[N_NODES * D];
// packed weights rows [Ws1|Wn1|Ws2|Wn2|Ws3|Wn3|Wp1(256 rows)] = 1024 x 128, [K][N]
__device__ __align__(16) bf16 g_wh[1024 * D];
__device__ __align__(16) bf16 g_wl[1024 * D];
// CSR
__device__ int g_cnt[N_NODES];
__device__ int g_rowptr[N_NODES + 1];
__device__ int g_csr[N_EDGES];
__device__ int g_bsum[NB_SCAN];
__device__ int g_boff[NB_SCAN];

// ---------------- CSR construction ----------------------------------------
__global__ void k_zero_cnt() {
    int i = blockIdx.x * blockDim.x + threadIdx.x;
    if (i < N_NODES) g_cnt[i] = 0;
}
__global__ void k_hist(const int* __restrict__ dst) {
    int e = blockIdx.x * blockDim.x + threadIdx.x;
    if (e < N_EDGES) atomicAdd(&g_cnt[dst[e]], 1);
}
// per-block exclusive scan -> rowptr (local), block total -> bsum
__global__ void k_blockscan() {
    __shared__ int sh[1024];
    int tid = threadIdx.x;
    int i = blockIdx.x * 1024 + tid;
    int v = (i < N_NODES) ? g_cnt[i] : 0;
    sh[tid] = v;
    __syncthreads();
    for (int o = 1; o < 1024; o <<= 1) {
        int t = (tid >= o) ? sh[tid - o] : 0;
        __syncthreads();
        sh[tid] += t;
        __syncthreads();
    }
    if (i < N_NODES) g_rowptr[i] = sh[tid] - v;   // local exclusive
    if (tid == 1023) g_bsum[blockIdx.x] = sh[1023];
}
// scan the 98 block totals with one 128-thread block
__global__ void k_scan_bsum() {
    __shared__ int sh[128];
    int t = threadIdx.x;
    int v = (t < NB_SCAN) ? g_bsum[t] : 0;
    sh[t] = v;
    __syncthreads();
    for (int o = 1; o < 128; o <<= 1) {
        int u = (t >= o) ? sh[t - o] : 0;
        __syncthreads();
        sh[t] += u;
        __syncthreads();
    }
    if (t < NB_SCAN) g_boff[t] = sh[t] - v;       // exclusive
    if (t == NB_SCAN - 1) g_rowptr[N_NODES] = sh[t];
}
// add block offsets and zero cnt (fused)
__global__ void k_addoff() {
    int i = blockIdx.x * blockDim.x + threadIdx.x;
    if (i < N_NODES) {
        g_rowptr[i] += g_boff[i >> 10];
        g_cnt[i] = 0;
    }
}
__global__ void k_place(const int* __restrict__ src, const int* __restrict__ dst) {
    int e = blockIdx.x * blockDim.x + threadIdx.x;
    if (e < N_EDGES) {
        int d = dst[e];
        int slot = g_rowptr[d] + atomicAdd(&g_cnt[d], 1);
        g_csr[slot] = src[e];
    }
}

// ---------------- conversions ----------------------------------------------
__device__ __forceinline__ void split_bf16(float v, bf16& h, bf16& l) {
    h = __float2bfloat16_rn(v);
    l = __float2bfloat16_rn(v - __bfloat162float(h));
}

__global__ void k_cvt4(const float* __restrict__ in, bf16* __restrict__ oh,
                       bf16* __restrict__ ol, int n4) {
    int i = blockIdx.x * blockDim.x + threadIdx.x;
    if (i >= n4) return;
    float4 v = ((const float4*)in)[i];
    bf16 hx, hy, hz, hw, lx, ly, lz, lw;
    split_bf16(v.x, hx, lx); split_bf16(v.y, hy, ly);
    split_bf16(v.z, hz, lz); split_bf16(v.w, hw, lw);
    bf162* ph = (bf162*)&oh[i * 4];
    bf162* pl = (bf162*)&ol[i * 4];
    ph[0] = __halves2bfloat162(hx, hy); ph[1] = __halves2bfloat162(hz, hw);
    pl[0] = __halves2bfloat162(lx, ly); pl[1] = __halves2bfloat162(lz, lw);
}

__global__ void k_cvt_w(const float* Ws1, const float* Wn1,
                        const float* Ws2, const float* Wn2,
                        const float* Ws3, const float* Wn3,
                        const float* Wp1) {
    int i = blockIdx.x * blockDim.x + threadIdx.x;   // 0 .. 1024*128-1
    if (i >= 1024 * D) return;
    int row = i >> 7, col = i & 127;
    const float* s; int lr;
    if      (row < 128)  { s = Ws1; lr = row; }
    else if (row < 256)  { s = Wn1; lr = row - 128; }
    else if (row < 384)  { s = Ws2; lr = row - 256; }
    else if (row < 512)  { s = Wn2; lr = row - 384; }
    else if (row < 640)  { s = Ws3; lr = row - 512; }
    else if (row < 768)  { s = Wn3; lr = row - 640; }
    else                 { s = Wp1; lr = row - 768; }
    float v = s[lr * D + col];
    bf16 h, l; split_bf16(v, h, l);
    g_wh[i] = h; g_wl[i] = l;
}

// ---------------- mean aggregation: reads bf16 hi/lo pair ------------------
__global__ void k_agg(const bf16* __restrict__ xh, const bf16* __restrict__ xl) {
    int gw   = (blockIdx.x * blockDim.x + threadIdx.x) >> 5;
    int lane = threadIdx.x & 31;
    if (gw >= N_NODES) return;
    int beg = g_rowptr[gw], end = g_rowptr[gw + 1];
    float4 acc = make_float4(0.f, 0.f, 0.f, 0.f);
    for (int e = beg; e < end; e++) {
        int idx = g_csr[e] * D + lane * 4;
        uint2 vh = *(const uint2*)&xh[idx];
        uint2 vl = *(const uint2*)&xl[idx];
        float2 h0 = __bfloat1622float2(*(bf162*)&vh.x);
        float2 h1 = __bfloat1622float2(*(bf162*)&vh.y);
        float2 l0 = __bfloat1622float2(*(bf162*)&vl.x);
        float2 l1 = __bfloat1622float2(*(bf162*)&vl.y);
        acc.x += h0.x + l0.x; acc.y += h0.y + l0.y;
        acc.z += h1.x + l1.x; acc.w += h1.y + l1.y;
    }
    int deg = end - beg;
    float inv = 1.0f / (float)(deg > 1 ? deg : 1);
    acc.x *= inv; acc.y *= inv; acc.z *= inv; acc.w *= inv;
    bf16 hx, hy, hz, hw, lx, ly, lz, lw;
    split_bf16(acc.x, hx, lx); split_bf16(acc.y, hy, ly);
    split_bf16(acc.z, hz, lz); split_bf16(acc.w, hw, lw);
    int idx = gw * D + lane * 4;
    bf162* ph = (bf162*)&g_mbh[idx];
    bf162* pl = (bf162*)&g_mbl[idx];
    ph[0] = __halves2bfloat162(hx, hy); ph[1] = __halves2bfloat162(hz, hw);
    pl[0] = __halves2bfloat162(lx, ly); pl[1] = __halves2bfloat162(lz, lw);
}

// ---------------- tensor-core GEMM (mma.sync, 2-stage, 2 CTA/SM) -----------
__device__ __forceinline__ void ldsm4(uint32_t& r0, uint32_t& r1, uint32_t& r2,
                                      uint32_t& r3, uint32_t addr) {
    asm volatile("ldmatrix.sync.aligned.m8n8.x4.shared.b16 {%0,%1,%2,%3}, [%4];"
                 : "=r"(r0), "=r"(r1), "=r"(r2), "=r"(r3) : "r"(addr));
}
__device__ __forceinline__ void ldsm4t(uint32_t& r0, uint32_t& r1, uint32_t& r2,
                                       uint32_t& r3, uint32_t addr) {
    asm volatile("ldmatrix.sync.aligned.m8n8.x4.trans.shared.b16 {%0,%1,%2,%3}, [%4];"
                 : "=r"(r0), "=r"(r1), "=r"(r2), "=r"(r3) : "r"(addr));
}
__device__ __forceinline__ void mma_bf16(float* c, const uint32_t* a, const uint32_t* b) {
    asm volatile(
        "mma.sync.aligned.m16n8k16.row.col.f32.bf16.bf16.f32 "
        "{%0,%1,%2,%3},{%4,%5,%6,%7},{%8,%9},{%0,%1,%2,%3};"
        : "+f"(c[0]), "+f"(c[1]), "+f"(c[2]), "+f"(c[3])
        : "r"(a[0]), "r"(a[1]), "r"(a[2]), "r"(a[3]), "r"(b[0]), "r"(b[1]));
}
__device__ __forceinline__ void cp16(uint32_t s, const void* g, bool p) {
    asm volatile("cp.async.cg.shared.global [%0], [%1], 16, %2;"
                 :: "r"(s), "l"(g), "r"(p ? 16 : 0));
}

#define A_STRIDE 80u        // bytes per A smem row (32 bf16 + pad)
#define B_STRIDE 272u       // bytes per B smem row (128 bf16 + pad)
#define A_BYTES (128u * A_STRIDE)   // 10240
#define B_BYTES (32u * B_STRIDE)    // 8704
#define STAGE (2u * A_BYTES + 2u * B_BYTES)  // 37888
#define GEMM_SMEM (2 * STAGE)                 // 75776 -> 2 CTAs/SM

// out[M,128] = (A1|A2)[M,K] @ W[K,128] + bias ; 3-term bf16 split.
// If out16a set (predictor): gridDim.y==2 selects weight block / output.
__global__ __launch_bounds__(256, 2) void k_gemm_tc(
    const bf16* __restrict__ A1h, const bf16* __restrict__ A1l,
    const bf16* __restrict__ A2h, const bf16* __restrict__ A2l,
    const bf16* __restrict__ Wh,  const bf16* __restrict__ Wl,
    const float* __restrict__ bias,
    bf16* __restrict__ outh, bf16* __restrict__ outl,
    __half* __restrict__ out16a, __half* __restrict__ out16b,
    int M, int K)
{
    extern __shared__ char sm[];
    uint32_t base = (uint32_t)__cvta_generic_to_shared(sm);

    __half* o16 = out16a;
    if (out16a && blockIdx.y == 1) {
        Wh += 128 * D; Wl += 128 * D;
        o16 = out16b; bias = nullptr;
    }

    int tid = threadIdx.x;
    int wid = tid >> 5, lane = tid & 31;
    int warp_m = (wid >> 2) * 64;
    int warp_n = (wid & 3) * 32;
    int m0 = blockIdx.x * 128;
    int nch = K / 32;          // 4 or 8

    float c[4][4][4];
    #pragma unroll
    for (int i = 0; i < 4; i++)
        #pragma unroll
        for (int j = 0; j < 4; j++)
            #pragma unroll
            for (int q = 0; q < 4; q++) c[i][j][q] = 0.f;

    auto load_chunk = [&](int ch) {
        uint32_t st = base + (uint32_t)(ch & 1) * STAGE;
        int kb = ch * 32;
        const bf16* Ah = (kb < 128) ? A1h : A2h;
        const bf16* Al = (kb < 128) ? A1l : A2l;
        int ac = kb & 127;
        #pragma unroll
        for (int l = tid; l < 512; l += 256) {      // A: 128 rows x 4 segs
            int r = l >> 2, seg = l & 3;
            uint32_t so = (uint32_t)r * A_STRIDE + (uint32_t)seg * 16u;
            bool p = (m0 + r) < M;
            int rr = p ? (m0 + r) : 0;
            size_t go = (size_t)rr * D + ac + seg * 8;
            cp16(st + so,           Ah + go, p);
            cp16(st + A_BYTES + so, Al + go, p);
        }
        #pragma unroll
        for (int l = tid; l < 512; l += 256) {      // B: 32 rows x 16 segs
            int r = l >> 4, seg = l & 15;
            uint32_t so = (uint32_t)r * B_STRIDE + (uint32_t)seg * 16u;
            size_t go = (size_t)(kb + r) * D + seg * 8;
            cp16(st + 2u * A_BYTES + so,           Wh + go, true);
            cp16(st + 2u * A_BYTES + B_BYTES + so, Wl + go, true);
        }
        asm volatile("cp.async.commit_group;" ::: "memory");
    };

    load_chunk(0);

    int lr = (lane & 7) + 8 * ((lane >> 3) & 1);
    int lc = 8 * (lane >> 4);

    for (int ch = 0; ch < nch; ch++) {
        asm volatile("cp.async.wait_group 0;" ::: "memory");
        __syncthreads();
        if (ch + 1 < nch) load_chunk(ch + 1);   // into stage freed last iter

        uint32_t st   = base + (uint32_t)(ch & 1) * STAGE;
        uint32_t ah_b = st;
        uint32_t al_b = st + A_BYTES;
        uint32_t bh_b = st + 2u * A_BYTES;
        uint32_t bl_b = bh_b + B_BYTES;

        #pragma unroll
        for (int ks = 0; ks < 2; ks++) {
            int k0 = ks * 16;
            uint32_t ah[4][4], al_[4][4];
            #pragma unroll
            for (int mi = 0; mi < 4; mi++) {
                uint32_t ro = (uint32_t)(warp_m + mi * 16 + lr) * A_STRIDE
                            + (uint32_t)(k0 + lc) * 2u;
                ldsm4(ah[mi][0], ah[mi][1], ah[mi][2], ah[mi][3], ah_b + ro);
                ldsm4(al_[mi][0], al_[mi][1], al_[mi][2], al_[mi][3], al_b + ro);
            }
            uint32_t bh[4][2], bl[4][2];
            #pragma unroll
            for (int njp = 0; njp < 2; njp++) {
                uint32_t ro = (uint32_t)(k0 + lr) * B_STRIDE
                            + (uint32_t)(warp_n + njp * 16 + lc) * 2u;
                uint32_t r0, r1, r2, r3;
                ldsm4t(r0, r1, r2, r3, bh_b + ro);
                bh[2 * njp][0] = r0;     bh[2 * njp][1] = r1;
                bh[2 * njp + 1][0] = r2; bh[2 * njp + 1][1] = r3;
                ldsm4t(r0, r1, r2, r3, bl_b + ro);
                bl[2 * njp][0] = r0;     bl[2 * njp][1] = r1;
                bl[2 * njp + 1][0] = r2; bl[2 * njp + 1][1] = r3;
            }
            #pragma unroll
            for (int mi = 0; mi < 4; mi++)
                #pragma unroll
                for (int nj = 0; nj < 4; nj++) {
                    mma_bf16(c[mi][nj], ah[mi], bh[nj]);
                    mma_bf16(c[mi][nj], ah[mi], bl[nj]);
                    mma_bf16(c[mi][nj], al_[mi], bh[nj]);
                }
        }
        if (ch + 1 < nch) __syncthreads();   // protect stage reuse vs slow warps
    }

    // epilogue
    #pragma unroll
    for (int mi = 0; mi < 4; mi++) {
        #pragma unroll
        for (int nj = 0; nj < 4; nj++) {
            int row0 = m0 + warp_m + mi * 16 + (lane >> 2);
            int col  = warp_n + nj * 8 + (lane & 3) * 2;
            float b0 = bias ? bias[col] : 0.f;
            float b1 = bias ? bias[col + 1] : 0.f;
            #pragma unroll
            for (int h = 0; h < 2; h++) {
                int row = row0 + 8 * h;
                if (row < M) {
                    float v0 = c[mi][nj][2 * h]     + b0;
                    float v1 = c[mi][nj][2 * h + 1] + b1;
                    if (o16) {
                        *(__half2*)&o16[(size_t)row * D + col] =
                            __floats2half2_rn(v0, v1);
                    } else {
                        bf16 h0, l0, h1, l1;
                        split_bf16(v0, h0, l0); split_bf16(v1, h1, l1);
                        *(bf162*)&outh[(size_t)row * D + col] = __halves2bfloat162(h0, h1);
                        *(bf162*)&outl[(size_t)row * D + col] = __halves2bfloat162(l0, l1);
                    }
                }
            }
        }
    }
}

// ---------------- edge scoring (fp16 projections) ---------------------------
__global__ void k_edge(const int* __restrict__ s1, const int* __restrict__ d1,
                       const int* __restrict__ s2, const int* __restrict__ d2,
                       const float* __restrict__ Wp2, const float* __restrict__ bp2,
                       float* __restrict__ out)
{
    int gw   = (blockIdx.x * blockDim.x + threadIdx.x) >> 5;
    int lane = threadIdx.x & 31;
    if (gw >= 2 * N_EDGES) return;
    int ss, dd;
    if (gw < N_EDGES) { ss = s1[gw]; dd = d1[gw]; }
    else              { ss = s2[gw - N_EDGES]; dd = d2[gw - N_EDGES]; }

    uint2 av = *(const uint2*)&g_pa16[(size_t)ss * D + lane * 4];
    uint2 bv = *(const uint2*)&g_pb16[(size_t)dd * D + lane * 4];
    float2 a0 = __half22float2(*(__half2*)&av.x);
    float2 a1 = __half22float2(*(__half2*)&av.y);
    float2 b0 = __half22float2(*(__half2*)&bv.x);
    float2 b1 = __half22float2(*(__half2*)&bv.y);
    float4 w = *(const float4*)&Wp2[lane * 4];

    float p = fmaxf(a0.x + b0.x, 0.f) * w.x
            + fmaxf(a0.y + b0.y, 0.f) * w.y
            + fmaxf(a1.x + b1.x, 0.f) * w.z
            + fmaxf(a1.y + b1.y, 0.f) * w.w;
    #pragma unroll
    for (int o = 16; o > 0; o >>= 1) p += __shfl_xor_sync(0xffffffffu, p, o);
    if (lane == 0) out[gw] = p + bp2[0];
}

// ---------------- launch ----------------------------------------------------
extern "C" void kernel_launch(void* const* d_in, const int* in_sizes, int n_in,
                              void* d_out, int out_size)
{
    const float* x    = (const float*)d_in[0];
    const int*   src  = (const int*)d_in[1];
    const int*   dst  = (const int*)d_in[2];
    const int*   nsrc = (const int*)d_in[3];
    const int*   ndst = (const int*)d_in[4];
    const float* Ws1 = (const float*)d_in[5],  *Wn1 = (const float*)d_in[6],  *b1 = (const float*)d_in[7];
    const float* Ws2 = (const float*)d_in[8],  *Wn2 = (const float*)d_in[9],  *b2 = (const float*)d_in[10];
    const float* Ws3 = (const float*)d_in[11], *Wn3 = (const float*)d_in[12], *b3 = (const float*)d_in[13];
    const float* Wp1 = (const float*)d_in[14], *bp1 = (const float*)d_in[15];
    const float* Wp2 = (const float*)d_in[16], *bp2 = (const float*)d_in[17];
    float* out = (float*)d_out;

    __half *p_pa16, *p_pb16;
    bf16 *p_xbh, *p_xbl, *p_mbh, *p_mbl, *p_h1h, *p_h1l, *p_h2h, *p_h2l, *p_wh, *p_wl;
    cudaGetSymbolAddress((void**)&p_pa16, g_pa16);
    cudaGetSymbolAddress((void**)&p_pb16, g_pb16);
    cudaGetSymbolAddress((void**)&p_xbh, g_xbh);
    cudaGetSymbolAddress((void**)&p_xbl, g_xbl);
    cudaGetSymbolAddress((void**)&p_mbh, g_mbh);
    cudaGetSymbolAddress((void**)&p_mbl, g_mbl);
    cudaGetSymbolAddress((void**)&p_h1h, g_h1h);
    cudaGetSymbolAddress((void**)&p_h1l, g_h1l);
    cudaGetSymbolAddress((void**)&p_h2h, g_h2h);
    cudaGetSymbolAddress((void**)&p_h2l, g_h2l);
    cudaGetSymbolAddress((void**)&p_wh, g_wh);
    cudaGetSymbolAddress((void**)&p_wl, g_wl);

    cudaFuncSetAttribute(k_gemm_tc, cudaFuncAttributeMaxDynamicSharedMemorySize,
                         GEMM_SMEM);

    // --- build CSR (6 launches) ---
    k_zero_cnt<<<(N_NODES + 255) / 256, 256>>>();
    k_hist<<<(N_EDGES + 255) / 256, 256>>>(dst);
    k_blockscan<<<NB_SCAN, 1024>>>();
    k_scan_bsum<<<1, 128>>>();
    k_addoff<<<(N_NODES + 255) / 256, 256>>>();
    k_place<<<(N_EDGES + 255) / 256, 256>>>(src, dst);

    // --- conversions ---
    int n4 = N_NODES * D / 4;
    k_cvt4<<<(n4 + 255) / 256, 256>>>(x, p_xbh, p_xbl, n4);
    k_cvt_w<<<(1024 * D + 255) / 256, 256>>>(Ws1, Wn1, Ws2, Wn2, Ws3, Wn3, Wp1);

    const int aggBlocks  = (N_NODES * 32 + 255) / 256;
    const int gemmBlocks = (N_NODES + 127) / 128;

    // --- layer 1 ---
    k_agg<<<aggBlocks, 256>>>(p_xbh, p_xbl);
    k_gemm_tc<<<gemmBlocks, 256, GEMM_SMEM>>>(p_xbh, p_xbl, p_mbh, p_mbl,
                                   p_wh, p_wl, b1,
                                   p_h1h, p_h1l, nullptr, nullptr, N_NODES, 256);
    // --- layer 2 ---
    k_agg<<<aggBlocks, 256>>>(p_h1h, p_h1l);
    k_gemm_tc<<<gemmBlocks, 256, GEMM_SMEM>>>(p_h1h, p_h1l, p_mbh, p_mbl,
                                   p_wh + 256 * D, p_wl + 256 * D, b2,
                                   p_h2h, p_h2l, nullptr, nullptr, N_NODES, 256);
    // --- layer 3 (write into h1 pair, free at this point) ---
    k_agg<<<aggBlocks, 256>>>(p_h2h, p_h2l);
    k_gemm_tc<<<gemmBlocks, 256, GEMM_SMEM>>>(p_h2h, p_h2l, p_mbh, p_mbl,
                                   p_wh + 512 * D, p_wl + 512 * D, b3,
                                   p_h1h, p_h1l, nullptr, nullptr, N_NODES, 256);

    // --- predictor projections (merged: gridDim.y=2 -> pa, pb in fp16) ---
    k_gemm_tc<<<dim3(gemmBlocks, 2), 256, GEMM_SMEM>>>(
                                   p_h1h, p_h1l, nullptr, nullptr,
                                   p_wh + 768 * D, p_wl + 768 * D, bp1,
                                   nullptr, nullptr, p_pa16, p_pb16, N_NODES, 128);

    // --- edge scores ---
    k_edge<<<(2 * N_EDGES * 32 + 255) / 256, 256>>>(src, dst, nsrc, ndst, Wp2, bp2, out);
}